// round 2
// baseline (speedup 1.0000x reference)
#include <cuda_runtime.h>
#include <cstdint>

#define EMBED 1024
#define HEADS 16
#define HDIM  64
#define BATCH 2
#define SEQ   2048
#define ROWSM (BATCH*SEQ)   // 4096

// ---------------- scratch (__device__ globals; no allocation allowed) ----------------
__device__ float g_M1 [EMBED*EMBED];
__device__ float g_M2 [EMBED*EMBED];
__device__ float g_Wqo[EMBED*EMBED];
__device__ float g_Wko[EMBED*EMBED];
__device__ float g_q  [ROWSM*EMBED];
__device__ float g_k  [ROWSM*EMBED];
__device__ float g_v  [ROWSM*EMBED];
__device__ float g_at [ROWSM*EMBED];
__device__ float g_sc [(size_t)BATCH*HEADS*SEQ*SEQ];   // 512 MB score scratch

// ---------------- helpers ----------------
__device__ __forceinline__ uint32_t f2tf32(float x) {
    uint32_t r;
    asm("cvt.rna.tf32.f32 %0, %1;\n" : "=r"(r) : "f"(x));
    return r;
}

// split fp32 into tf32 hi + tf32 lo (captures ~21 mantissa bits)
__device__ __forceinline__ void split_tf32(float f, uint32_t& hi, uint32_t& lo) {
    hi = f2tf32(f);
    lo = f2tf32(f - __uint_as_float(hi));
}

__device__ __forceinline__ void mma_tf32(float (&d)[4], const uint32_t (&a)[4],
                                         const uint32_t (&b)[2], const float (&c)[4]) {
    asm volatile(
        "mma.sync.aligned.m16n8k8.row.col.f32.tf32.tf32.f32 "
        "{%0,%1,%2,%3},{%4,%5,%6,%7},{%8,%9},{%10,%11,%12,%13};\n"
        : "=f"(d[0]), "=f"(d[1]), "=f"(d[2]), "=f"(d[3])
        : "r"(a[0]), "r"(a[1]), "r"(a[2]), "r"(a[3]),
          "r"(b[0]), "r"(b[1]),
          "f"(c[0]), "f"(c[1]), "f"(c[2]), "f"(c[3]));
}

// ---------------- generic batched split-tf32 (fp32-accurate) GEMM ----------------
// C = alpha * opA(A) * opB(B) [+ beta * Cin]
// opA(A)[m,k] = TA ? A[k*lda+m] : A[m*lda+k]
// opB(B)[k,n] = TB ? B[n*ldb+k] : B[k*ldb+n]
template<int BM, int BN, int BK, int WM, int WN, bool TA, bool TB, bool HASC>
__global__ void __launch_bounds__((BM/WM)*(BN/WN)*32)
gemm_tf32(const float* __restrict__ Aall, const float* __restrict__ Ball,
          const float* __restrict__ Cin,  float* __restrict__ Call,
          int M, int N, int K, int lda, int ldb, int ldc,
          float alpha, float beta,
          long long sAo, long long sAi, long long sBo, long long sBi,
          long long sCo, long long sCi, int innerB)
{
    constexpr int WARPS_N = BN / WN;
    constexpr int WARPS_M = BM / WM;
    constexpr int NTHREADS = WARPS_M * WARPS_N * 32;
    constexpr int MFRAG = WM / 16, NFRAG = WN / 8, KSTEPS = BK / 8;
    constexpr int LDA_S = TA ? (BM + 8) : (BK + 4);
    constexpr int LDB_S = TB ? (BK + 4) : (BN + 8);

    __shared__ float As[TA ? (BK * LDA_S) : (BM * LDA_S)];
    __shared__ float Bs[TB ? (BN * LDB_S) : (BK * LDB_S)];

    const int z = blockIdx.z;
    const long long ob = z / innerB, ib = z % innerB;
    const float* A = Aall + ob * sAo + ib * sAi;
    const float* B = Ball + ob * sBo + ib * sBi;
    float*       C = Call + ob * sCo + ib * sCi;

    const int mbase = blockIdx.y * BM;
    const int nbase = blockIdx.x * BN;
    const int tid  = threadIdx.x;
    const int warp = tid >> 5, lane = tid & 31;
    const int wm = warp / WARPS_N, wn = warp % WARPS_N;
    const int gq = lane >> 2, tq = lane & 3;

    float acc[MFRAG][NFRAG][4];
#pragma unroll
    for (int i = 0; i < MFRAG; i++)
#pragma unroll
        for (int j = 0; j < NFRAG; j++)
#pragma unroll
            for (int r = 0; r < 4; r++) acc[i][j][r] = 0.f;

    for (int kb = 0; kb < K; kb += BK) {
        // ---- cooperative load A tile (raw fp32 in shared) ----
        if (TA) {
#pragma unroll
            for (int e = tid; e < BM * BK; e += NTHREADS) {
                int k = e / BM, m = e % BM;
                As[k * LDA_S + m] = A[(size_t)(kb + k) * lda + mbase + m];
            }
        } else {
#pragma unroll
            for (int e = tid; e < BM * BK; e += NTHREADS) {
                int m = e / BK, k = e % BK;
                As[m * LDA_S + k] = A[(size_t)(mbase + m) * lda + kb + k];
            }
        }
        // ---- cooperative load B tile ----
        if (TB) {
#pragma unroll
            for (int e = tid; e < BN * BK; e += NTHREADS) {
                int n = e / BK, k = e % BK;
                Bs[n * LDB_S + k] = B[(size_t)(nbase + n) * ldb + kb + k];
            }
        } else {
#pragma unroll
            for (int e = tid; e < BN * BK; e += NTHREADS) {
                int k = e / BN, n = e % BN;
                Bs[k * LDB_S + n] = B[(size_t)(kb + k) * ldb + nbase + n];
            }
        }
        __syncthreads();

#pragma unroll
        for (int ks = 0; ks < KSTEPS; ks++) {
            const int k0 = ks * 8 + tq;
            uint32_t ah[MFRAG][4], al[MFRAG][4];
            uint32_t bh[NFRAG][2], bl[NFRAG][2];
#pragma unroll
            for (int fm = 0; fm < MFRAG; fm++) {
                const int m0 = wm * WM + fm * 16 + gq;
                float f0, f1, f2, f3;
                if (TA) {
                    f0 = As[(k0)     * LDA_S + m0];
                    f1 = As[(k0)     * LDA_S + m0 + 8];
                    f2 = As[(k0 + 4) * LDA_S + m0];
                    f3 = As[(k0 + 4) * LDA_S + m0 + 8];
                } else {
                    f0 = As[(m0)     * LDA_S + k0];
                    f1 = As[(m0 + 8) * LDA_S + k0];
                    f2 = As[(m0)     * LDA_S + k0 + 4];
                    f3 = As[(m0 + 8) * LDA_S + k0 + 4];
                }
                split_tf32(f0, ah[fm][0], al[fm][0]);
                split_tf32(f1, ah[fm][1], al[fm][1]);
                split_tf32(f2, ah[fm][2], al[fm][2]);
                split_tf32(f3, ah[fm][3], al[fm][3]);
            }
#pragma unroll
            for (int fn = 0; fn < NFRAG; fn++) {
                const int n0 = wn * WN + fn * 8 + gq;
                float f0, f1;
                if (TB) {
                    f0 = Bs[n0 * LDB_S + k0];
                    f1 = Bs[n0 * LDB_S + k0 + 4];
                } else {
                    f0 = Bs[(k0)     * LDB_S + n0];
                    f1 = Bs[(k0 + 4) * LDB_S + n0];
                }
                split_tf32(f0, bh[fn][0], bl[fn][0]);
                split_tf32(f1, bh[fn][1], bl[fn][1]);
            }
#pragma unroll
            for (int fm = 0; fm < MFRAG; fm++)
#pragma unroll
                for (int fn = 0; fn < NFRAG; fn++) {
                    // small terms first, then dominant hi*hi
                    mma_tf32(acc[fm][fn], al[fm], bh[fn], acc[fm][fn]);
                    mma_tf32(acc[fm][fn], ah[fm], bl[fn], acc[fm][fn]);
                    mma_tf32(acc[fm][fn], ah[fm], bh[fn], acc[fm][fn]);
                }
        }
        __syncthreads();
    }

    // ---- epilogue ----
#pragma unroll
    for (int fm = 0; fm < MFRAG; fm++) {
        const int m0 = mbase + wm * WM + fm * 16 + gq;
#pragma unroll
        for (int fn = 0; fn < NFRAG; fn++) {
            const int n0 = nbase + wn * WN + fn * 8 + tq * 2;
            float* c0 = C + (size_t)m0 * ldc + n0;
            float* c1 = C + (size_t)(m0 + 8) * ldc + n0;
            if (HASC) {
                const float* ci0 = Cin + (size_t)m0 * ldc + n0;
                const float* ci1 = Cin + (size_t)(m0 + 8) * ldc + n0;
                c0[0] = alpha * acc[fm][fn][0] + beta * ci0[0];
                c0[1] = alpha * acc[fm][fn][1] + beta * ci0[1];
                c1[0] = alpha * acc[fm][fn][2] + beta * ci1[0];
                c1[1] = alpha * acc[fm][fn][3] + beta * ci1[1];
            } else {
                c0[0] = alpha * acc[fm][fn][0];
                c0[1] = alpha * acc[fm][fn][1];
                c1[0] = alpha * acc[fm][fn][2];
                c1[1] = alpha * acc[fm][fn][3];
            }
        }
    }
}

// ---------------- row softmax over SEQ=2048-wide rows ----------------
__global__ void __launch_bounds__(256) softmax_rows(float* __restrict__ s)
{
    const size_t row = blockIdx.x;
    float* p = s + row * (size_t)SEQ;
    const int tid = threadIdx.x;
    const int lane = tid & 31, warp = tid >> 5;

    float vals[8];
    float mx = -1e30f;
#pragma unroll
    for (int i = 0; i < 8; i++) {
        vals[i] = p[tid + i * 256];
        mx = fmaxf(mx, vals[i]);
    }
#pragma unroll
    for (int o = 16; o > 0; o >>= 1) mx = fmaxf(mx, __shfl_xor_sync(0xffffffffu, mx, o));

    __shared__ float red[8];
    if (lane == 0) red[warp] = mx;
    __syncthreads();
    float bm = red[0];
#pragma unroll
    for (int i = 1; i < 8; i++) bm = fmaxf(bm, red[i]);
    __syncthreads();

    float sum = 0.f;
#pragma unroll
    for (int i = 0; i < 8; i++) {
        vals[i] = __expf(vals[i] - bm);
        sum += vals[i];
    }
#pragma unroll
    for (int o = 16; o > 0; o >>= 1) sum += __shfl_xor_sync(0xffffffffu, sum, o);
    if (lane == 0) red[warp] = sum;
    __syncthreads();
    float bs = 0.f;
#pragma unroll
    for (int i = 0; i < 8; i++) bs += red[i];
    const float inv = 1.f / bs;
#pragma unroll
    for (int i = 0; i < 8; i++) p[tid + i * 256] = vals[i] * inv;
}

// ---------------- host launch ----------------
extern "C" void kernel_launch(void* const* d_in, const int* in_sizes, int n_in,
                              void* d_out, int out_size)
{
    (void)in_sizes; (void)n_in; (void)out_size;
    const float* query = (const float*)d_in[0];
    const float* key   = (const float*)d_in[1];
    const float* value = (const float*)d_in[2];
    const float* Wq    = (const float*)d_in[3];
    const float* Wk    = (const float*)d_in[4];
    const float* Wv    = (const float*)d_in[5];
    const float* Wo    = (const float*)d_in[6];
    float* out = (float*)d_out;

    float *M1, *M2, *Wqo, *Wko, *q, *k, *v, *at, *sc;
    cudaGetSymbolAddress((void**)&M1,  g_M1);
    cudaGetSymbolAddress((void**)&M2,  g_M2);
    cudaGetSymbolAddress((void**)&Wqo, g_Wqo);
    cudaGetSymbolAddress((void**)&Wko, g_Wko);
    cudaGetSymbolAddress((void**)&q,   g_q);
    cudaGetSymbolAddress((void**)&k,   g_k);
    cudaGetSymbolAddress((void**)&v,   g_v);
    cudaGetSymbolAddress((void**)&at,  g_at);
    cudaGetSymbolAddress((void**)&sc,  g_sc);

    const dim3 blk(256);

    // 1,2: M1 = Wk^T Wk ; M2 = Wq^T Wq   (1024^3)
    {
        dim3 grid(EMBED / 128, EMBED / 128, 1);
        gemm_tf32<128,128,32,64,32,true,false,false><<<grid, blk>>>(
            Wk, Wk, nullptr, M1, EMBED, EMBED, EMBED, EMBED, EMBED, EMBED,
            1.f, 0.f, 0,0,0,0,0,0, 1);
        gemm_tf32<128,128,32,64,32,true,false,false><<<grid, blk>>>(
            Wq, Wq, nullptr, M2, EMBED, EMBED, EMBED, EMBED, EMBED, EMBED,
            1.f, 0.f, 0,0,0,0,0,0, 1);
        // 3,4: Wqo = Wq - Wq@M1 ; Wko = Wk - Wk@M2
        gemm_tf32<128,128,32,64,32,false,false,true><<<grid, blk>>>(
            Wq, M1, Wq, Wqo, EMBED, EMBED, EMBED, EMBED, EMBED, EMBED,
            -1.f, 1.f, 0,0,0,0,0,0, 1);
        gemm_tf32<128,128,32,64,32,false,false,true><<<grid, blk>>>(
            Wk, M2, Wk, Wko, EMBED, EMBED, EMBED, EMBED, EMBED, EMBED,
            -1.f, 1.f, 0,0,0,0,0,0, 1);
    }

    // 5-7: projections  X[4096,1024] @ W^T
    {
        dim3 grid(EMBED / 128, ROWSM / 128, 1);
        gemm_tf32<128,128,32,64,32,false,true,false><<<grid, blk>>>(
            query, Wqo, nullptr, q, ROWSM, EMBED, EMBED, EMBED, EMBED, EMBED,
            1.f, 0.f, 0,0,0,0,0,0, 1);
        gemm_tf32<128,128,32,64,32,false,true,false><<<grid, blk>>>(
            key, Wko, nullptr, k, ROWSM, EMBED, EMBED, EMBED, EMBED, EMBED,
            1.f, 0.f, 0,0,0,0,0,0, 1);
        gemm_tf32<128,128,32,64,32,false,true,false><<<grid, blk>>>(
            value, Wv, nullptr, v, ROWSM, EMBED, EMBED, EMBED, EMBED, EMBED,
            1.f, 0.f, 0,0,0,0,0,0, 1);
    }

    // 8: scores[b,h] = 0.125 * Q_bh @ K_bh^T   (batched: 32 x [2048,2048,64])
    {
        dim3 grid(SEQ / 128, SEQ / 128, BATCH * HEADS);
        gemm_tf32<128,128,32,64,32,false,true,false><<<grid, blk>>>(
            q, k, nullptr, sc, SEQ, SEQ, HDIM, EMBED, EMBED, SEQ,
            0.125f, 0.f,
            (long long)SEQ * EMBED, (long long)HDIM,
            (long long)SEQ * EMBED, (long long)HDIM,
            (long long)HEADS * SEQ * SEQ, (long long)SEQ * SEQ,
            HEADS);
    }

    // 9: softmax over rows
    softmax_rows<<<BATCH * HEADS * SEQ, 256>>>(sc);

    // 10: attn_out[b,h] = P @ V_bh  (batched: 32 x [2048,64,2048]), written to [B,S,E] layout
    {
        dim3 grid(HDIM / 64, SEQ / 128, BATCH * HEADS);
        gemm_tf32<128,64,32,32,32,false,false,false><<<grid, blk>>>(
            sc, v, nullptr, at, SEQ, HDIM, SEQ, SEQ, EMBED, EMBED,
            1.f, 0.f,
            (long long)HEADS * SEQ * SEQ, (long long)SEQ * SEQ,
            (long long)SEQ * EMBED, (long long)HDIM,
            (long long)SEQ * EMBED, (long long)HDIM,
            HEADS);
    }

    // 11: out = attn_out @ Wo^T
    {
        dim3 grid(EMBED / 128, ROWSM / 128, 1);
        gemm_tf32<128,128,32,64,32,false,true,false><<<grid, blk>>>(
            at, Wo, nullptr, out, ROWSM, EMBED, EMBED, EMBED, EMBED, EMBED,
            1.f, 0.f, 0,0,0,0,0,0, 1);
    }
}

// round 3
// speedup vs baseline: 1.4393x; 1.4393x over previous
#include <cuda_runtime.h>
#include <cuda_fp16.h>
#include <cstdint>

#define EMBED 1024
#define HEADS 16
#define HDIM  64
#define BATCH 2
#define SEQ   2048
#define ROWSM (BATCH*SEQ)   // 4096

// ---------------- scratch (__device__ globals; no allocation allowed) ----------------
__device__ float g_M1 [EMBED*EMBED];
__device__ float g_M2 [EMBED*EMBED];
__device__ float g_Wqo[EMBED*EMBED];
__device__ float g_Wko[EMBED*EMBED];
__device__ float g_q  [ROWSM*EMBED];
__device__ float g_k  [ROWSM*EMBED];
__device__ float g_v  [ROWSM*EMBED];
__device__ float g_at [ROWSM*EMBED];
__device__ float g_sc [(size_t)BATCH*HEADS*SEQ*SEQ];   // 512 MB score scratch

// ---------------- helpers ----------------
// split fp32 into fp16 hi + fp16 lo (captures ~22 mantissa bits)
__device__ __forceinline__ void split_f16(float f, __half& hi, __half& lo) {
    hi = __float2half_rn(f);
    lo = __float2half_rn(f - __half2float(hi));
}

__device__ __forceinline__ void mma_f16(float (&d)[4], const uint32_t (&a)[4],
                                        const uint32_t (&b)[2], const float (&c)[4]) {
    asm volatile(
        "mma.sync.aligned.m16n8k16.row.col.f32.f16.f16.f32 "
        "{%0,%1,%2,%3},{%4,%5,%6,%7},{%8,%9},{%10,%11,%12,%13};\n"
        : "=f"(d[0]), "=f"(d[1]), "=f"(d[2]), "=f"(d[3])
        : "r"(a[0]), "r"(a[1]), "r"(a[2]), "r"(a[3]),
          "r"(b[0]), "r"(b[1]),
          "f"(c[0]), "f"(c[1]), "f"(c[2]), "f"(c[3]));
}

// ---------------- generic batched split-fp16 (fp32-accurate) GEMM ----------------
// C = alpha * opA(A) * opB(B) [+ beta * Cin]
// opA(A)[m,k] = TA ? A[k*lda+m] : A[m*lda+k]
// opB(B)[k,n] = TB ? B[n*ldb+k] : B[k*ldb+n]
// smem always holds A as [m][k], B as [n][k] (k-major), in hi and lo fp16 planes.
template<int BM, int BN, int BK, int WM, int WN, bool TA, bool TB, bool HASC>
__global__ void __launch_bounds__((BM/WM)*(BN/WN)*32)
gemm_f16s(const float* __restrict__ Aall, const float* __restrict__ Ball,
          const float* __restrict__ Cin,  float* __restrict__ Call,
          int M, int N, int K, int lda, int ldb, int ldc,
          float alpha, float beta,
          long long sAo, long long sAi, long long sBo, long long sBi,
          long long sCo, long long sCi, int innerB)
{
    constexpr int WARPS_N = BN / WN;
    constexpr int WARPS_M = BM / WM;
    constexpr int NTHREADS = WARPS_M * WARPS_N * 32;
    constexpr int MFRAG = WM / 16, NFRAG = WN / 8, KSTEPS = BK / 16;
    constexpr int LDK = BK + 8;   // halves; even -> half2 aligned; 20-word rows -> conflict-free frags

    __shared__ __half As[2][BM * LDK];
    __shared__ __half Bs[2][BN * LDK];

    const int z = blockIdx.z;
    const long long ob = z / innerB, ib = z % innerB;
    const float* A = Aall + ob * sAo + ib * sAi;
    const float* B = Ball + ob * sBo + ib * sBi;
    float*       C = Call + ob * sCo + ib * sCi;

    const int mbase = blockIdx.y * BM;
    const int nbase = blockIdx.x * BN;
    const int tid  = threadIdx.x;
    const int warp = tid >> 5, lane = tid & 31;
    const int wm = warp / WARPS_N, wn = warp % WARPS_N;
    const int gq = lane >> 2, tq = lane & 3;

    float acc[MFRAG][NFRAG][4];
#pragma unroll
    for (int i = 0; i < MFRAG; i++)
#pragma unroll
        for (int j = 0; j < NFRAG; j++)
#pragma unroll
            for (int r = 0; r < 4; r++) acc[i][j][r] = 0.f;

    for (int kb = 0; kb < K; kb += BK) {
        // ---- cooperative load + split A tile ----
#pragma unroll
        for (int e = tid; e < BM * BK; e += NTHREADS) {
            int m, k;
            if (TA) { k = e / BM; m = e % BM; }      // gmem coalesced along m
            else    { m = e / BK; k = e % BK; }      // gmem coalesced along k
            float f = TA ? A[(size_t)(kb + k) * lda + mbase + m]
                         : A[(size_t)(mbase + m) * lda + kb + k];
            __half h, l; split_f16(f, h, l);
            As[0][m * LDK + k] = h;
            As[1][m * LDK + k] = l;
        }
        // ---- cooperative load + split B tile ----
#pragma unroll
        for (int e = tid; e < BN * BK; e += NTHREADS) {
            int n, k;
            if (TB) { n = e / BK; k = e % BK; }
            else    { k = e / BN; n = e % BN; }
            float f = TB ? B[(size_t)(nbase + n) * ldb + kb + k]
                         : B[(size_t)(kb + k) * ldb + nbase + n];
            __half h, l; split_f16(f, h, l);
            Bs[0][n * LDK + k] = h;
            Bs[1][n * LDK + k] = l;
        }
        __syncthreads();

#pragma unroll
        for (int ks = 0; ks < KSTEPS; ks++) {
            const int k0 = ks * 16 + 2 * tq;   // even
            uint32_t ah[MFRAG][4], al[MFRAG][4];
            uint32_t bh[NFRAG][2], bl[NFRAG][2];
#pragma unroll
            for (int fm = 0; fm < MFRAG; fm++) {
                const int m0 = wm * WM + fm * 16 + gq;
#pragma unroll
                for (int p = 0; p < 2; p++) {
                    uint32_t* dst = p ? al[fm] : ah[fm];
                    const __half* base = As[p];
                    dst[0] = *(const uint32_t*)&base[(m0)     * LDK + k0];
                    dst[1] = *(const uint32_t*)&base[(m0 + 8) * LDK + k0];
                    dst[2] = *(const uint32_t*)&base[(m0)     * LDK + k0 + 8];
                    dst[3] = *(const uint32_t*)&base[(m0 + 8) * LDK + k0 + 8];
                }
            }
#pragma unroll
            for (int fn = 0; fn < NFRAG; fn++) {
                const int n0 = wn * WN + fn * 8 + gq;
#pragma unroll
                for (int p = 0; p < 2; p++) {
                    uint32_t* dst = p ? bl[fn] : bh[fn];
                    const __half* base = Bs[p];
                    dst[0] = *(const uint32_t*)&base[n0 * LDK + k0];
                    dst[1] = *(const uint32_t*)&base[n0 * LDK + k0 + 8];
                }
            }
#pragma unroll
            for (int fm = 0; fm < MFRAG; fm++)
#pragma unroll
                for (int fn = 0; fn < NFRAG; fn++) {
                    // small terms first, then dominant hi*hi
                    mma_f16(acc[fm][fn], al[fm], bh[fn], acc[fm][fn]);
                    mma_f16(acc[fm][fn], ah[fm], bl[fn], acc[fm][fn]);
                    mma_f16(acc[fm][fn], ah[fm], bh[fn], acc[fm][fn]);
                }
        }
        __syncthreads();
    }

    // ---- epilogue ----
#pragma unroll
    for (int fm = 0; fm < MFRAG; fm++) {
        const int m0 = mbase + wm * WM + fm * 16 + gq;
#pragma unroll
        for (int fn = 0; fn < NFRAG; fn++) {
            const int n0 = nbase + wn * WN + fn * 8 + tq * 2;
            float* c0 = C + (size_t)m0 * ldc + n0;
            float* c1 = C + (size_t)(m0 + 8) * ldc + n0;
            if (HASC) {
                const float* ci0 = Cin + (size_t)m0 * ldc + n0;
                const float* ci1 = Cin + (size_t)(m0 + 8) * ldc + n0;
                c0[0] = alpha * acc[fm][fn][0] + beta * ci0[0];
                c0[1] = alpha * acc[fm][fn][1] + beta * ci0[1];
                c1[0] = alpha * acc[fm][fn][2] + beta * ci1[0];
                c1[1] = alpha * acc[fm][fn][3] + beta * ci1[1];
            } else {
                c0[0] = alpha * acc[fm][fn][0];
                c0[1] = alpha * acc[fm][fn][1];
                c1[0] = alpha * acc[fm][fn][2];
                c1[1] = alpha * acc[fm][fn][3];
            }
        }
    }
}

// ---------------- row softmax over SEQ=2048-wide rows ----------------
__global__ void __launch_bounds__(256) softmax_rows(float* __restrict__ s)
{
    const size_t row = blockIdx.x;
    float* p = s + row * (size_t)SEQ;
    const int tid = threadIdx.x;
    const int lane = tid & 31, warp = tid >> 5;

    float vals[8];
    float mx = -1e30f;
#pragma unroll
    for (int i = 0; i < 8; i++) {
        vals[i] = p[tid + i * 256];
        mx = fmaxf(mx, vals[i]);
    }
#pragma unroll
    for (int o = 16; o > 0; o >>= 1) mx = fmaxf(mx, __shfl_xor_sync(0xffffffffu, mx, o));

    __shared__ float red[8];
    if (lane == 0) red[warp] = mx;
    __syncthreads();
    float bm = red[0];
#pragma unroll
    for (int i = 1; i < 8; i++) bm = fmaxf(bm, red[i]);
    __syncthreads();

    float sum = 0.f;
#pragma unroll
    for (int i = 0; i < 8; i++) {
        vals[i] = __expf(vals[i] - bm);
        sum += vals[i];
    }
#pragma unroll
    for (int o = 16; o > 0; o >>= 1) sum += __shfl_xor_sync(0xffffffffu, sum, o);
    if (lane == 0) red[warp] = sum;
    __syncthreads();
    float bs = 0.f;
#pragma unroll
    for (int i = 0; i < 8; i++) bs += red[i];
    const float inv = 1.f / bs;
#pragma unroll
    for (int i = 0; i < 8; i++) p[tid + i * 256] = vals[i] * inv;
}

// ---------------- host launch ----------------
extern "C" void kernel_launch(void* const* d_in, const int* in_sizes, int n_in,
                              void* d_out, int out_size)
{
    (void)in_sizes; (void)n_in; (void)out_size;
    const float* query = (const float*)d_in[0];
    const float* key   = (const float*)d_in[1];
    const float* value = (const float*)d_in[2];
    const float* Wq    = (const float*)d_in[3];
    const float* Wk    = (const float*)d_in[4];
    const float* Wv    = (const float*)d_in[5];
    const float* Wo    = (const float*)d_in[6];
    float* out = (float*)d_out;

    float *M1, *M2, *Wqo, *Wko, *q, *k, *v, *at, *sc;
    cudaGetSymbolAddress((void**)&M1,  g_M1);
    cudaGetSymbolAddress((void**)&M2,  g_M2);
    cudaGetSymbolAddress((void**)&Wqo, g_Wqo);
    cudaGetSymbolAddress((void**)&Wko, g_Wko);
    cudaGetSymbolAddress((void**)&q,   g_q);
    cudaGetSymbolAddress((void**)&k,   g_k);
    cudaGetSymbolAddress((void**)&v,   g_v);
    cudaGetSymbolAddress((void**)&at,  g_at);
    cudaGetSymbolAddress((void**)&sc,  g_sc);

    // 1,2: M1 = Wk^T Wk ; M2 = Wq^T Wq   (1024^3, 64x64 tiles -> 256 blocks)
    {
        dim3 grid(EMBED / 64, EMBED / 64, 1);
        gemm_f16s<64,64,32,32,32,true,false,false><<<grid, 128>>>(
            Wk, Wk, nullptr, M1, EMBED, EMBED, EMBED, EMBED, EMBED, EMBED,
            1.f, 0.f, 0,0,0,0,0,0, 1);
        gemm_f16s<64,64,32,32,32,true,false,false><<<grid, 128>>>(
            Wq, Wq, nullptr, M2, EMBED, EMBED, EMBED, EMBED, EMBED, EMBED,
            1.f, 0.f, 0,0,0,0,0,0, 1);
        // 3,4: Wqo = Wq - Wq@M1 ; Wko = Wk - Wk@M2
        gemm_f16s<64,64,32,32,32,false,false,true><<<grid, 128>>>(
            Wq, M1, Wq, Wqo, EMBED, EMBED, EMBED, EMBED, EMBED, EMBED,
            -1.f, 1.f, 0,0,0,0,0,0, 1);
        gemm_f16s<64,64,32,32,32,false,false,true><<<grid, 128>>>(
            Wk, M2, Wk, Wko, EMBED, EMBED, EMBED, EMBED, EMBED, EMBED,
            -1.f, 1.f, 0,0,0,0,0,0, 1);
    }

    // 5-7: projections  X[4096,1024] @ W^T
    {
        dim3 grid(EMBED / 128, ROWSM / 128, 1);
        gemm_f16s<128,128,32,64,32,false,true,false><<<grid, 256>>>(
            query, Wqo, nullptr, q, ROWSM, EMBED, EMBED, EMBED, EMBED, EMBED,
            1.f, 0.f, 0,0,0,0,0,0, 1);
        gemm_f16s<128,128,32,64,32,false,true,false><<<grid, 256>>>(
            key, Wko, nullptr, k, ROWSM, EMBED, EMBED, EMBED, EMBED, EMBED,
            1.f, 0.f, 0,0,0,0,0,0, 1);
        gemm_f16s<128,128,32,64,32,false,true,false><<<grid, 256>>>(
            value, Wv, nullptr, v, ROWSM, EMBED, EMBED, EMBED, EMBED, EMBED,
            1.f, 0.f, 0,0,0,0,0,0, 1);
    }

    // 8: scores[b,h] = 0.125 * Q_bh @ K_bh^T   (batched: 32 x [2048,2048,64])
    {
        dim3 grid(SEQ / 128, SEQ / 128, BATCH * HEADS);
        gemm_f16s<128,128,32,64,32,false,true,false><<<grid, 256>>>(
            q, k, nullptr, sc, SEQ, SEQ, HDIM, EMBED, EMBED, SEQ,
            0.125f, 0.f,
            (long long)SEQ * EMBED, (long long)HDIM,
            (long long)SEQ * EMBED, (long long)HDIM,
            (long long)HEADS * SEQ * SEQ, (long long)SEQ * SEQ,
            HEADS);
    }

    // 9: softmax over rows
    softmax_rows<<<BATCH * HEADS * SEQ, 256>>>(sc);

    // 10: attn_out[b,h] = P @ V_bh  (batched: 32 x [2048,64,2048])
    {
        dim3 grid(HDIM / 64, SEQ / 128, BATCH * HEADS);
        gemm_f16s<128,64,32,32,32,false,false,false><<<grid, 256>>>(
            sc, v, nullptr, at, SEQ, HDIM, SEQ, SEQ, EMBED, EMBED,
            1.f, 0.f,
            (long long)HEADS * SEQ * SEQ, (long long)SEQ * SEQ,
            (long long)SEQ * EMBED, (long long)HDIM,
            (long long)SEQ * EMBED, (long long)HDIM,
            HEADS);
    }

    // 11: out = attn_out @ Wo^T
    {
        dim3 grid(EMBED / 128, ROWSM / 128, 1);
        gemm_f16s<128,128,32,64,32,false,true,false><<<grid, 256>>>(
            at, Wo, nullptr, out, ROWSM, EMBED, EMBED, EMBED, EMBED, EMBED,
            1.f, 0.f, 0,0,0,0,0,0, 1);
    }
}

// round 4
// speedup vs baseline: 2.5546x; 1.7749x over previous
#include <cuda_runtime.h>
#include <cuda_fp16.h>
#include <cstdint>

#define EMBED 1024
#define HEADS 16
#define HDIM  64
#define BATCH 2
#define SEQ   2048
#define ROWSM (BATCH*SEQ)   // 4096
#define EE    (EMBED*EMBED)
#define RME   (ROWSM*EMBED)

// ---------------- scratch (__device__ globals; no allocation allowed) ----------------
__device__ float g_Wcat[2*EE];   // [Wq, Wk] staged
__device__ float g_Mcat[2*EE];   // [Wk^T Wk, Wq^T Wq]
__device__ float g_Wall[3*EE];   // [Wqo, Wko, Wv]
__device__ float g_X   [3*RME];  // [query, key, value] staged
__device__ float g_qkv [3*RME];  // [q, k, v] projected
__device__ float g_at  [RME];    // attention output

// ---------------- helpers ----------------
__device__ __forceinline__ void split_f16(float f, __half& hi, __half& lo) {
    hi = __float2half_rn(f);
    lo = __float2half_rn(f - __half2float(hi));
}
__device__ __forceinline__ void split2(float a, float b, uint32_t& hi, uint32_t& lo) {
    __half2 h = __floats2half2_rn(a, b);
    float2 hf = __half22float2(h);
    __half2 l = __floats2half2_rn(a - hf.x, b - hf.y);
    hi = *reinterpret_cast<uint32_t*>(&h);
    lo = *reinterpret_cast<uint32_t*>(&l);
}
__device__ __forceinline__ uint32_t pack_h2(float a, float b) {
    __half2 h = __floats2half2_rn(a, b);
    return *reinterpret_cast<uint32_t*>(&h);
}

__device__ __forceinline__ void mma_f16(float (&d)[4], const uint32_t (&a)[4],
                                        const uint32_t (&b)[2], const float (&c)[4]) {
    asm volatile(
        "mma.sync.aligned.m16n8k16.row.col.f32.f16.f16.f32 "
        "{%0,%1,%2,%3},{%4,%5,%6,%7},{%8,%9},{%10,%11,%12,%13};\n"
        : "=f"(d[0]), "=f"(d[1]), "=f"(d[2]), "=f"(d[3])
        : "r"(a[0]), "r"(a[1]), "r"(a[2]), "r"(a[3]),
          "r"(b[0]), "r"(b[1]),
          "f"(c[0]), "f"(c[1]), "f"(c[2]), "f"(c[3]));
}

// ---------------- generic batched split-fp16 GEMM with register prefetch ----------------
// C = alpha * opA(A) * opB(B) [+ beta * Cin]
template<int BM, int BN, int BK, int WM, int WN, bool TA, bool TB, bool HASC>
__global__ void __launch_bounds__((BM/WM)*(BN/WN)*32)
gemm_f16s(const float* __restrict__ Aall, const float* __restrict__ Ball,
          const float* __restrict__ Cinall, float* __restrict__ Call,
          int M, int N, int K, int lda, int ldb, int ldc,
          float alpha, float beta,
          long long sAo, long long sAi, long long sBo, long long sBi,
          long long sCo, long long sCi, int innerB)
{
    constexpr int WARPS_N = BN / WN;
    constexpr int WARPS_M = BM / WM;
    constexpr int NT = WARPS_M * WARPS_N * 32;
    constexpr int MFRAG = WM / 16, NFRAG = WN / 8, KSTEPS = BK / 16;
    constexpr int LDK = BK + 8;
    constexpr int EA = BM * BK / NT, EB = BN * BK / NT;

    __shared__ __half As[2][BM * LDK];
    __shared__ __half Bs[2][BN * LDK];

    const int z = blockIdx.z;
    const long long ob = z / innerB, ib = z % innerB;
    const float* A = Aall + ob * sAo + ib * sAi;
    const float* B = Ball + ob * sBo + ib * sBi;
    float*       C = Call + ob * sCo + ib * sCi;
    const float* Cin = HASC ? (Cinall + ob * sCo + ib * sCi) : nullptr;

    const int mbase = blockIdx.y * BM;
    const int nbase = blockIdx.x * BN;
    const int tid  = threadIdx.x;
    const int warp = tid >> 5, lane = tid & 31;
    const int wm = warp / WARPS_N, wn = warp % WARPS_N;
    const int gq = lane >> 2, tq = lane & 3;

    float acc[MFRAG][NFRAG][4];
#pragma unroll
    for (int i = 0; i < MFRAG; i++)
#pragma unroll
        for (int j = 0; j < NFRAG; j++)
#pragma unroll
            for (int r = 0; r < 4; r++) acc[i][j][r] = 0.f;

    float ra[EA], rb[EB];

    auto ldA = [&](int kb) {
#pragma unroll
        for (int i = 0; i < EA; i++) {
            int e = i * NT + tid; int m, k;
            if (TA) { k = e / BM; m = e % BM; } else { m = e / BK; k = e % BK; }
            ra[i] = TA ? A[(size_t)(kb + k) * lda + mbase + m]
                       : A[(size_t)(mbase + m) * lda + kb + k];
        }
    };
    auto ldB = [&](int kb) {
#pragma unroll
        for (int i = 0; i < EB; i++) {
            int e = i * NT + tid; int n, k;
            if (TB) { n = e / BK; k = e % BK; } else { k = e / BN; n = e % BN; }
            rb[i] = TB ? B[(size_t)(nbase + n) * ldb + kb + k]
                       : B[(size_t)(kb + k) * ldb + nbase + n];
        }
    };
    auto stAB = [&]() {
#pragma unroll
        for (int i = 0; i < EA; i++) {
            int e = i * NT + tid; int m, k;
            if (TA) { k = e / BM; m = e % BM; } else { m = e / BK; k = e % BK; }
            __half h, l; split_f16(ra[i], h, l);
            As[0][m * LDK + k] = h;
            As[1][m * LDK + k] = l;
        }
#pragma unroll
        for (int i = 0; i < EB; i++) {
            int e = i * NT + tid; int n, k;
            if (TB) { n = e / BK; k = e % BK; } else { k = e / BN; n = e % BN; }
            __half h, l; split_f16(rb[i], h, l);
            Bs[0][n * LDK + k] = h;
            Bs[1][n * LDK + k] = l;
        }
    };

    ldA(0); ldB(0);

    for (int kb = 0; kb < K; kb += BK) {
        stAB();
        __syncthreads();
        if (kb + BK < K) { ldA(kb + BK); ldB(kb + BK); }   // prefetch overlaps MMAs

#pragma unroll
        for (int ks = 0; ks < KSTEPS; ks++) {
            const int k0 = ks * 16 + 2 * tq;
            uint32_t ah[MFRAG][4], al[MFRAG][4];
            uint32_t bh[NFRAG][2], bl[NFRAG][2];
#pragma unroll
            for (int fm = 0; fm < MFRAG; fm++) {
                const int m0 = wm * WM + fm * 16 + gq;
#pragma unroll
                for (int p = 0; p < 2; p++) {
                    uint32_t* dst = p ? al[fm] : ah[fm];
                    const __half* base = As[p];
                    dst[0] = *(const uint32_t*)&base[(m0)     * LDK + k0];
                    dst[1] = *(const uint32_t*)&base[(m0 + 8) * LDK + k0];
                    dst[2] = *(const uint32_t*)&base[(m0)     * LDK + k0 + 8];
                    dst[3] = *(const uint32_t*)&base[(m0 + 8) * LDK + k0 + 8];
                }
            }
#pragma unroll
            for (int fn = 0; fn < NFRAG; fn++) {
                const int n0 = wn * WN + fn * 8 + gq;
#pragma unroll
                for (int p = 0; p < 2; p++) {
                    uint32_t* dst = p ? bl[fn] : bh[fn];
                    const __half* base = Bs[p];
                    dst[0] = *(const uint32_t*)&base[n0 * LDK + k0];
                    dst[1] = *(const uint32_t*)&base[n0 * LDK + k0 + 8];
                }
            }
#pragma unroll
            for (int fm = 0; fm < MFRAG; fm++)
#pragma unroll
                for (int fn = 0; fn < NFRAG; fn++) {
                    mma_f16(acc[fm][fn], al[fm], bh[fn], acc[fm][fn]);
                    mma_f16(acc[fm][fn], ah[fm], bl[fn], acc[fm][fn]);
                    mma_f16(acc[fm][fn], ah[fm], bh[fn], acc[fm][fn]);
                }
        }
        __syncthreads();
    }

    // ---- epilogue ----
#pragma unroll
    for (int fm = 0; fm < MFRAG; fm++) {
        const int m0 = mbase + wm * WM + fm * 16 + gq;
#pragma unroll
        for (int fn = 0; fn < NFRAG; fn++) {
            const int n0 = nbase + wn * WN + fn * 8 + tq * 2;
            float* c0 = C + (size_t)m0 * ldc + n0;
            float* c1 = C + (size_t)(m0 + 8) * ldc + n0;
            if (HASC) {
                const float* ci0 = Cin + (size_t)m0 * ldc + n0;
                const float* ci1 = Cin + (size_t)(m0 + 8) * ldc + n0;
                c0[0] = alpha * acc[fm][fn][0] + beta * ci0[0];
                c0[1] = alpha * acc[fm][fn][1] + beta * ci0[1];
                c1[0] = alpha * acc[fm][fn][2] + beta * ci1[0];
                c1[1] = alpha * acc[fm][fn][3] + beta * ci1[1];
            } else {
                c0[0] = alpha * acc[fm][fn][0];
                c0[1] = alpha * acc[fm][fn][1];
                c1[0] = alpha * acc[fm][fn][2];
                c1[1] = alpha * acc[fm][fn][3];
            }
        }
    }
}

// ---------------- fused flash attention ----------------
// grid(32 heads, 16 q-tiles), 256 threads (8 warps x 16 q-rows), BQ=128, BKV=128.
// K smem: [128 kv][72] halves x2 planes. V smem transposed: [64 d][136 kv] x2 planes.
#define FA_LDK 72
#define FA_LDV 136
#define FA_SMEM ((2*128*FA_LDK + 2*64*FA_LDV) * 2)

__global__ void __launch_bounds__(256)
flash_attn(const float* __restrict__ qkv, float* __restrict__ outb)
{
    extern __shared__ __half sm[];
    __half* Ks0 = sm;
    __half* Ks1 = Ks0 + 128 * FA_LDK;
    __half* Vs0 = Ks1 + 128 * FA_LDK;
    __half* Vs1 = Vs0 + 64 * FA_LDV;

    const int hh = blockIdx.x;            // 0..31
    const int b = hh >> 4, h = hh & 15;
    const int qt = blockIdx.y;            // 0..15

    const float* Qb = qkv + ((size_t)b * SEQ) * EMBED + h * HDIM;
    const float* Kb = Qb + (size_t)RME;
    const float* Vb = Qb + 2 * (size_t)RME;

    const int tid = threadIdx.x;
    const int w = tid >> 5, lane = tid & 31;
    const int gq = lane >> 2, tq = lane & 3;

    // ---- Q fragments in registers (pre-scaled, split hi/lo) ----
    uint32_t qh[4][4], ql[4][4];
    {
        const int r0 = qt * 128 + w * 16 + gq;
        const float* Qr0 = Qb + (size_t)r0 * EMBED;
        const float* Qr1 = Qr0 + 8 * (size_t)EMBED;
#pragma unroll
        for (int ks = 0; ks < 4; ks++) {
            const int c = 16 * ks + 2 * tq;
            float2 x0 = *(const float2*)(Qr0 + c);
            float2 x1 = *(const float2*)(Qr1 + c);
            float2 x2 = *(const float2*)(Qr0 + c + 8);
            float2 x3 = *(const float2*)(Qr1 + c + 8);
            split2(x0.x * 0.125f, x0.y * 0.125f, qh[ks][0], ql[ks][0]);
            split2(x1.x * 0.125f, x1.y * 0.125f, qh[ks][1], ql[ks][1]);
            split2(x2.x * 0.125f, x2.y * 0.125f, qh[ks][2], ql[ks][2]);
            split2(x3.x * 0.125f, x3.y * 0.125f, qh[ks][3], ql[ks][3]);
        }
    }

    float o[8][4];
#pragma unroll
    for (int i = 0; i < 8; i++)
#pragma unroll
        for (int r = 0; r < 4; r++) o[i][r] = 0.f;
    float m0r = -1e30f, m1r = -1e30f, l0 = 0.f, l1 = 0.f;

    for (int j = 0; j < SEQ / 128; j++) {
        // ---- load K tile [128][64] -> Ks (split) ----
        const float* Kt = Kb + (size_t)(j * 128) * EMBED;
#pragma unroll
        for (int i = 0; i < 16; i++) {
            int idx = i * 256 + tid;
            int row = idx >> 5, c2 = idx & 31;
            float2 x = *(const float2*)(Kt + (size_t)row * EMBED + 2 * c2);
            uint32_t hi, lo; split2(x.x, x.y, hi, lo);
            *(uint32_t*)&Ks0[row * FA_LDK + 2 * c2] = hi;
            *(uint32_t*)&Ks1[row * FA_LDK + 2 * c2] = lo;
        }
        // ---- load V tile transposed [64 d][128 kv] -> Vs (split) ----
        const float* Vt = Vb + (size_t)(j * 128) * EMBED;
#pragma unroll
        for (int i = 0; i < 16; i++) {
            int idx = i * 256 + tid;
            int d = idx & 63, rp = idx >> 6;        // kv pair 2rp, 2rp+1
            const float* vb0 = Vt + (size_t)(2 * rp) * EMBED + d;
            float x0 = vb0[0];
            float x1 = vb0[EMBED];
            uint32_t hi, lo; split2(x0, x1, hi, lo);
            *(uint32_t*)&Vs0[d * FA_LDV + 2 * rp] = hi;
            *(uint32_t*)&Vs1[d * FA_LDV + 2 * rp] = lo;
        }
        __syncthreads();

        // ---- S = Q K^T (split 3-plane) ----
        float s[16][4];
#pragma unroll
        for (int f = 0; f < 16; f++)
#pragma unroll
            for (int r = 0; r < 4; r++) s[f][r] = 0.f;
#pragma unroll
        for (int ks = 0; ks < 4; ks++) {
            const int k0 = 16 * ks + 2 * tq;
#pragma unroll
            for (int fn = 0; fn < 16; fn++) {
                const int n0 = fn * 8 + gq;
                uint32_t bh[2], bl[2];
                bh[0] = *(const uint32_t*)&Ks0[n0 * FA_LDK + k0];
                bh[1] = *(const uint32_t*)&Ks0[n0 * FA_LDK + k0 + 8];
                bl[0] = *(const uint32_t*)&Ks1[n0 * FA_LDK + k0];
                bl[1] = *(const uint32_t*)&Ks1[n0 * FA_LDK + k0 + 8];
                mma_f16(s[fn], ql[ks], bh, s[fn]);
                mma_f16(s[fn], qh[ks], bl, s[fn]);
                mma_f16(s[fn], qh[ks], bh, s[fn]);
            }
        }

        // ---- online softmax ----
        float mx0 = -1e30f, mx1 = -1e30f;
#pragma unroll
        for (int f = 0; f < 16; f++) {
            mx0 = fmaxf(mx0, fmaxf(s[f][0], s[f][1]));
            mx1 = fmaxf(mx1, fmaxf(s[f][2], s[f][3]));
        }
        mx0 = fmaxf(mx0, __shfl_xor_sync(0xffffffffu, mx0, 1));
        mx0 = fmaxf(mx0, __shfl_xor_sync(0xffffffffu, mx0, 2));
        mx1 = fmaxf(mx1, __shfl_xor_sync(0xffffffffu, mx1, 1));
        mx1 = fmaxf(mx1, __shfl_xor_sync(0xffffffffu, mx1, 2));
        const float mn0 = fmaxf(m0r, mx0), mn1 = fmaxf(m1r, mx1);
        const float cr0 = __expf(m0r - mn0), cr1 = __expf(m1r - mn1);
        m0r = mn0; m1r = mn1;

        float rs0 = 0.f, rs1 = 0.f;
#pragma unroll
        for (int f = 0; f < 16; f++) {
            s[f][0] = __expf(s[f][0] - mn0);
            s[f][1] = __expf(s[f][1] - mn0);
            s[f][2] = __expf(s[f][2] - mn1);
            s[f][3] = __expf(s[f][3] - mn1);
            rs0 += s[f][0] + s[f][1];
            rs1 += s[f][2] + s[f][3];
        }
        rs0 += __shfl_xor_sync(0xffffffffu, rs0, 1);
        rs0 += __shfl_xor_sync(0xffffffffu, rs0, 2);
        rs1 += __shfl_xor_sync(0xffffffffu, rs1, 1);
        rs1 += __shfl_xor_sync(0xffffffffu, rs1, 2);
        l0 = l0 * cr0 + rs0;
        l1 = l1 * cr1 + rs1;
#pragma unroll
        for (int fn = 0; fn < 8; fn++) {
            o[fn][0] *= cr0; o[fn][1] *= cr0;
            o[fn][2] *= cr1; o[fn][3] *= cr1;
        }

        // ---- O += P V : P in-register (fp16), V split ----
#pragma unroll
        for (int ks = 0; ks < 8; ks++) {
            uint32_t pa[4];
            pa[0] = pack_h2(s[2*ks][0],   s[2*ks][1]);
            pa[1] = pack_h2(s[2*ks][2],   s[2*ks][3]);
            pa[2] = pack_h2(s[2*ks+1][0], s[2*ks+1][1]);
            pa[3] = pack_h2(s[2*ks+1][2], s[2*ks+1][3]);
            const int k0 = 16 * ks + 2 * tq;
#pragma unroll
            for (int fn = 0; fn < 8; fn++) {
                const int n0 = fn * 8 + gq;
                uint32_t bh[2], bl[2];
                bh[0] = *(const uint32_t*)&Vs0[n0 * FA_LDV + k0];
                bh[1] = *(const uint32_t*)&Vs0[n0 * FA_LDV + k0 + 8];
                bl[0] = *(const uint32_t*)&Vs1[n0 * FA_LDV + k0];
                bl[1] = *(const uint32_t*)&Vs1[n0 * FA_LDV + k0 + 8];
                mma_f16(o[fn], pa, bh, o[fn]);
                mma_f16(o[fn], pa, bl, o[fn]);
            }
        }
        __syncthreads();
    }

    // ---- write out ----
    const float inv0 = 1.f / l0, inv1 = 1.f / l1;
    const int r0 = qt * 128 + w * 16 + gq;
    float* Ob0 = outb + ((size_t)(b * SEQ + r0)) * EMBED + h * HDIM;
    float* Ob1 = Ob0 + 8 * (size_t)EMBED;
#pragma unroll
    for (int fn = 0; fn < 8; fn++) {
        const int c = fn * 8 + 2 * tq;
        float2 t0; t0.x = o[fn][0] * inv0; t0.y = o[fn][1] * inv0;
        float2 t1; t1.x = o[fn][2] * inv1; t1.y = o[fn][3] * inv1;
        *(float2*)(Ob0 + c) = t0;
        *(float2*)(Ob1 + c) = t1;
    }
}

// ---------------- host launch ----------------
extern "C" void kernel_launch(void* const* d_in, const int* in_sizes, int n_in,
                              void* d_out, int out_size)
{
    (void)in_sizes; (void)n_in; (void)out_size;
    const float* query = (const float*)d_in[0];
    const float* key   = (const float*)d_in[1];
    const float* value = (const float*)d_in[2];
    const float* Wq    = (const float*)d_in[3];
    const float* Wk    = (const float*)d_in[4];
    const float* Wv    = (const float*)d_in[5];
    const float* Wo    = (const float*)d_in[6];
    float* out = (float*)d_out;

    float *Wcat, *Mcat, *Wall, *X, *qkv, *at;
    cudaGetSymbolAddress((void**)&Wcat, g_Wcat);
    cudaGetSymbolAddress((void**)&Mcat, g_Mcat);
    cudaGetSymbolAddress((void**)&Wall, g_Wall);
    cudaGetSymbolAddress((void**)&X,    g_X);
    cudaGetSymbolAddress((void**)&qkv,  g_qkv);
    cudaGetSymbolAddress((void**)&at,   g_at);

    // stage inputs for batched GEMMs (D2D, capture-legal)
    cudaMemcpyAsync(Wcat,        Wq,    (size_t)EE  * 4, cudaMemcpyDeviceToDevice, 0);
    cudaMemcpyAsync(Wcat + EE,   Wk,    (size_t)EE  * 4, cudaMemcpyDeviceToDevice, 0);
    cudaMemcpyAsync(Wall + 2*EE, Wv,    (size_t)EE  * 4, cudaMemcpyDeviceToDevice, 0);
    cudaMemcpyAsync(X,           query, (size_t)RME * 4, cudaMemcpyDeviceToDevice, 0);
    cudaMemcpyAsync(X + RME,     key,   (size_t)RME * 4, cudaMemcpyDeviceToDevice, 0);
    cudaMemcpyAsync(X + 2*RME,   value, (size_t)RME * 4, cudaMemcpyDeviceToDevice, 0);

    // 1: Mcat[z] = W[1-z]^T W[1-z]   (z=0: Wk^T Wk, z=1: Wq^T Wq)
    {
        dim3 grid(EMBED / 64, EMBED / 64, 2);
        gemm_f16s<64,64,32,32,32,true,false,false><<<grid, 128>>>(
            Wcat + EE, Wcat + EE, nullptr, Mcat,
            EMBED, EMBED, EMBED, EMBED, EMBED, EMBED,
            1.f, 0.f, 0, -(long long)EE, 0, -(long long)EE, 0, (long long)EE, 2);
    }
    // 2: Wall[z] = Wcat[z] - Wcat[z] @ Mcat[z]   (z=0: Wqo, z=1: Wko)
    {
        dim3 grid(EMBED / 64, EMBED / 64, 2);
        gemm_f16s<64,64,32,32,32,false,false,true><<<grid, 128>>>(
            Wcat, Mcat, Wcat, Wall,
            EMBED, EMBED, EMBED, EMBED, EMBED, EMBED,
            -1.f, 1.f, 0, (long long)EE, 0, (long long)EE, 0, (long long)EE, 2);
    }
    // 3: qkv[z] = X[z] @ Wall[z]^T   (batched z=3)
    {
        dim3 grid(EMBED / 128, ROWSM / 128, 3);
        gemm_f16s<128,128,32,64,32,false,true,false><<<grid, 256>>>(
            X, Wall, nullptr, qkv,
            ROWSM, EMBED, EMBED, EMBED, EMBED, EMBED,
            1.f, 0.f, 0, (long long)RME, 0, (long long)EE, 0, (long long)RME, 3);
    }
    // 4: fused flash attention -> at
    {
        cudaFuncSetAttribute(flash_attn, cudaFuncAttributeMaxDynamicSharedMemorySize, FA_SMEM);
        dim3 grid(BATCH * HEADS, SEQ / 128);
        flash_attn<<<grid, 256, FA_SMEM>>>(qkv, at);
    }
    // 5: out = at @ Wo^T
    {
        dim3 grid(EMBED / 128, ROWSM / 128, 1);
        gemm_f16s<128,128,32,64,32,false,true,false><<<grid, 256>>>(
            at, Wo, nullptr, out,
            ROWSM, EMBED, EMBED, EMBED, EMBED, EMBED,
            1.f, 0.f, 0, 0, 0, 0, 0, 0, 1);
    }
}

// round 5
// speedup vs baseline: 3.1743x; 1.2426x over previous
#include <cuda_runtime.h>
#include <cuda_fp16.h>
#include <cstdint>

#define EMBED 1024
#define HEADS 16
#define HDIM  64
#define BATCH 2
#define SEQ   2048
#define ROWSM (BATCH*SEQ)   // 4096
#define EE    (EMBED*EMBED)
#define RME   (ROWSM*EMBED)

// ---------------- scratch (__device__ globals; no allocation allowed) ----------------
__device__ float g_Mcat[2*EE];   // [Wk^T Wk, Wq^T Wq]
__device__ float g_Wo2 [2*EE];   // [Wqo, Wko]
__device__ float g_qkv [3*RME];  // [q, k, v] projected
__device__ float g_at  [RME];    // attention output

// ---------------- helpers ----------------
__device__ __forceinline__ void split_f16(float f, __half& hi, __half& lo) {
    hi = __float2half_rn(f);
    lo = __float2half_rn(f - __half2float(hi));
}
__device__ __forceinline__ void split2(float a, float b, uint32_t& hi, uint32_t& lo) {
    __half2 h = __floats2half2_rn(a, b);
    float2 hf = __half22float2(h);
    __half2 l = __floats2half2_rn(a - hf.x, b - hf.y);
    hi = *reinterpret_cast<uint32_t*>(&h);
    lo = *reinterpret_cast<uint32_t*>(&l);
}
__device__ __forceinline__ uint32_t pack_h2(float a, float b) {
    __half2 h = __floats2half2_rn(a, b);
    return *reinterpret_cast<uint32_t*>(&h);
}

__device__ __forceinline__ void mma_f16(float (&d)[4], const uint32_t (&a)[4],
                                        const uint32_t (&b)[2], const float (&c)[4]) {
    asm volatile(
        "mma.sync.aligned.m16n8k16.row.col.f32.f16.f16.f32 "
        "{%0,%1,%2,%3},{%4,%5,%6,%7},{%8,%9},{%10,%11,%12,%13};\n"
        : "=f"(d[0]), "=f"(d[1]), "=f"(d[2]), "=f"(d[3])
        : "r"(a[0]), "r"(a[1]), "r"(a[2]), "r"(a[3]),
          "r"(b[0]), "r"(b[1]),
          "f"(c[0]), "f"(c[1]), "f"(c[2]), "f"(c[3]));
}

__device__ __forceinline__ uint32_t sptr(const void* p) {
    return (uint32_t)__cvta_generic_to_shared(p);
}
__device__ __forceinline__ void ldmx4(uint32_t* r, const __half* p) {
    asm volatile("ldmatrix.sync.aligned.m8n8.x4.shared.b16 {%0,%1,%2,%3}, [%4];"
        : "=r"(r[0]), "=r"(r[1]), "=r"(r[2]), "=r"(r[3]) : "r"(sptr(p)));
}

// ---------------- generic 3-way batched split-fp16 GEMM, ldmatrix frags ----------------
// z = blockIdx.z selects (A,B,Cin,C) pointer set.
// C = alpha * opA(A) * opB(B) [+ beta * Cin]
// SPLITA: A uses hi+lo planes (3 MMAs) else hi only (2 MMAs). B always split.
template<int BM, int BN, int BK, int WM, int WN, bool TA, bool TB, bool HASC, bool SPLITA>
__global__ void __launch_bounds__((BM/WM)*(BN/WN)*32)
gemm_f16s(const float* __restrict__ A0, const float* __restrict__ A1, const float* __restrict__ A2,
          const float* __restrict__ B0, const float* __restrict__ B1, const float* __restrict__ B2,
          const float* __restrict__ Ci0, const float* __restrict__ Ci1, const float* __restrict__ Ci2,
          float* __restrict__ C0, float* __restrict__ C1, float* __restrict__ C2,
          int M, int N, int K, int lda, int ldb, int ldc,
          float alpha, float beta)
{
    constexpr int WARPS_N = BN / WN;
    constexpr int WARPS_M = BM / WM;
    constexpr int NT = WARPS_M * WARPS_N * 32;
    constexpr int MFRAG = WM / 16, NFRAG = WN / 8, KSTEPS = BK / 16;
    constexpr int LDK = BK + 8;
    constexpr int EA = BM * BK / NT, EB = BN * BK / NT;
    constexpr int APLANES = SPLITA ? 2 : 1;

    __shared__ __half As[APLANES * BM * LDK];
    __shared__ __half Bs[2 * BN * LDK];

    const int z = blockIdx.z;
    const float* A = (z == 0) ? A0 : ((z == 1) ? A1 : A2);
    const float* B = (z == 0) ? B0 : ((z == 1) ? B1 : B2);
    const float* Cin = (z == 0) ? Ci0 : ((z == 1) ? Ci1 : Ci2);
    float*       C = (z == 0) ? C0 : ((z == 1) ? C1 : C2);

    const int mbase = blockIdx.y * BM;
    const int nbase = blockIdx.x * BN;
    const int tid  = threadIdx.x;
    const int warp = tid >> 5, lane = tid & 31;
    const int wm = warp / WARPS_N, wn = warp % WARPS_N;
    const int gq = lane >> 2, tq = lane & 3;

    float acc[MFRAG][NFRAG][4];
#pragma unroll
    for (int i = 0; i < MFRAG; i++)
#pragma unroll
        for (int j = 0; j < NFRAG; j++)
#pragma unroll
            for (int r = 0; r < 4; r++) acc[i][j][r] = 0.f;

    float ra[EA], rb[EB];

    auto ldA = [&](int kb) {
#pragma unroll
        for (int i = 0; i < EA; i++) {
            int e = i * NT + tid; int m, k;
            if (TA) { k = e / BM; m = e % BM; } else { m = e / BK; k = e % BK; }
            ra[i] = TA ? A[(size_t)(kb + k) * lda + mbase + m]
                       : A[(size_t)(mbase + m) * lda + kb + k];
        }
    };
    auto ldB = [&](int kb) {
#pragma unroll
        for (int i = 0; i < EB; i++) {
            int e = i * NT + tid; int n, k;
            if (TB) { n = e / BK; k = e % BK; } else { k = e / BN; n = e % BN; }
            rb[i] = TB ? B[(size_t)(nbase + n) * ldb + kb + k]
                       : B[(size_t)(kb + k) * ldb + nbase + n];
        }
    };
    auto stAB = [&]() {
#pragma unroll
        for (int i = 0; i < EA; i++) {
            int e = i * NT + tid; int m, k;
            if (TA) { k = e / BM; m = e % BM; } else { m = e / BK; k = e % BK; }
            if (SPLITA) {
                __half h, l; split_f16(ra[i], h, l);
                As[m * LDK + k] = h;
                As[BM * LDK + m * LDK + k] = l;
            } else {
                As[m * LDK + k] = __float2half_rn(ra[i]);
            }
        }
#pragma unroll
        for (int i = 0; i < EB; i++) {
            int e = i * NT + tid; int n, k;
            if (TB) { n = e / BK; k = e % BK; } else { k = e / BN; n = e % BN; }
            __half h, l; split_f16(rb[i], h, l);
            Bs[n * LDK + k] = h;
            Bs[BN * LDK + n * LDK + k] = l;
        }
    };

    ldA(0); ldB(0);

    // ldmatrix lane addressing (constant across ks except k offset)
    const int a_row = (lane & 15);             // row within 16
    const int a_kof = (lane >> 4) << 3;        // 0 or 8
    const int b_row = (lane & 7) + (((lane >> 4) & 1) << 3);  // row within 16 (fn pair)
    const int b_kof = ((lane >> 3) & 1) << 3;  // 0 or 8

    for (int kb = 0; kb < K; kb += BK) {
        stAB();
        __syncthreads();
        if (kb + BK < K) { ldA(kb + BK); ldB(kb + BK); }   // prefetch overlaps MMAs

#pragma unroll
        for (int ks = 0; ks < KSTEPS; ks++) {
            const int k0 = ks * 16;
            uint32_t ah[MFRAG][4], al[MFRAG][4];
            uint32_t bh[NFRAG][2], bl[NFRAG][2];
#pragma unroll
            for (int fm = 0; fm < MFRAG; fm++) {
                const int mr = wm * WM + fm * 16 + a_row;
                ldmx4(ah[fm], &As[mr * LDK + k0 + a_kof]);
                if (SPLITA)
                    ldmx4(al[fm], &As[BM * LDK + mr * LDK + k0 + a_kof]);
            }
#pragma unroll
            for (int fp = 0; fp < NFRAG / 2; fp++) {
                const int nr = wn * WN + fp * 16 + b_row;
                uint32_t t[4];
                ldmx4(t, &Bs[nr * LDK + k0 + b_kof]);
                bh[2*fp][0] = t[0]; bh[2*fp][1] = t[1];
                bh[2*fp+1][0] = t[2]; bh[2*fp+1][1] = t[3];
                ldmx4(t, &Bs[BN * LDK + nr * LDK + k0 + b_kof]);
                bl[2*fp][0] = t[0]; bl[2*fp][1] = t[1];
                bl[2*fp+1][0] = t[2]; bl[2*fp+1][1] = t[3];
            }
#pragma unroll
            for (int fm = 0; fm < MFRAG; fm++)
#pragma unroll
                for (int fn = 0; fn < NFRAG; fn++) {
                    if (SPLITA) mma_f16(acc[fm][fn], al[fm], bh[fn], acc[fm][fn]);
                    mma_f16(acc[fm][fn], ah[fm], bl[fn], acc[fm][fn]);
                    mma_f16(acc[fm][fn], ah[fm], bh[fn], acc[fm][fn]);
                }
        }
        __syncthreads();
    }

    // ---- epilogue ----
#pragma unroll
    for (int fm = 0; fm < MFRAG; fm++) {
        const int m0 = mbase + wm * WM + fm * 16 + gq;
#pragma unroll
        for (int fn = 0; fn < NFRAG; fn++) {
            const int n0 = nbase + wn * WN + fn * 8 + tq * 2;
            float* c0 = C + (size_t)m0 * ldc + n0;
            float* c1 = C + (size_t)(m0 + 8) * ldc + n0;
            if (HASC) {
                const float* ci0 = Cin + (size_t)m0 * ldc + n0;
                const float* ci1 = Cin + (size_t)(m0 + 8) * ldc + n0;
                c0[0] = alpha * acc[fm][fn][0] + beta * ci0[0];
                c0[1] = alpha * acc[fm][fn][1] + beta * ci0[1];
                c1[0] = alpha * acc[fm][fn][2] + beta * ci1[0];
                c1[1] = alpha * acc[fm][fn][3] + beta * ci1[1];
            } else {
                c0[0] = alpha * acc[fm][fn][0];
                c0[1] = alpha * acc[fm][fn][1];
                c1[0] = alpha * acc[fm][fn][2];
                c1[1] = alpha * acc[fm][fn][3];
            }
        }
    }
}

// ---------------- fused flash attention ----------------
// grid(32 heads, 16 q-tiles), 256 threads, BQ=128, BKV=128.
// K smem: 2 planes [128 kv][72]; V smem: 1 plane transposed [64 d][136 kv].
#define FA_LDK 72
#define FA_LDV 136
#define FA_SMEM ((2*128*FA_LDK + 64*FA_LDV) * 2)

__global__ void __launch_bounds__(256)
flash_attn(const float* __restrict__ qkv, float* __restrict__ outb)
{
    extern __shared__ __half sm[];
    __half* Ks0 = sm;
    __half* Ks1 = Ks0 + 128 * FA_LDK;
    __half* Vs0 = Ks1 + 128 * FA_LDK;

    const int hh = blockIdx.x;            // 0..31
    const int b = hh >> 4, h = hh & 15;
    const int qt = blockIdx.y;            // 0..15

    const float* Qb = qkv + ((size_t)b * SEQ) * EMBED + h * HDIM;
    const float* Kb = Qb + (size_t)RME;
    const float* Vb = Qb + 2 * (size_t)RME;

    const int tid = threadIdx.x;
    const int w = tid >> 5, lane = tid & 31;
    const int gq = lane >> 2, tq = lane & 3;

    // ldmatrix lane addressing
    const int a_row = (lane & 15);
    const int a_kof = (lane >> 4) << 3;
    const int b_row = (lane & 7) + (((lane >> 4) & 1) << 3);
    const int b_kof = ((lane >> 3) & 1) << 3;

    // ---- Q fragments in registers (pre-scaled, split hi/lo) ----
    uint32_t qh[4][4], ql[4][4];
    {
        const int r0 = qt * 128 + w * 16 + gq;
        const float* Qr0 = Qb + (size_t)r0 * EMBED;
        const float* Qr1 = Qr0 + 8 * (size_t)EMBED;
#pragma unroll
        for (int ks = 0; ks < 4; ks++) {
            const int c = 16 * ks + 2 * tq;
            float2 x0 = *(const float2*)(Qr0 + c);
            float2 x1 = *(const float2*)(Qr1 + c);
            float2 x2 = *(const float2*)(Qr0 + c + 8);
            float2 x3 = *(const float2*)(Qr1 + c + 8);
            split2(x0.x * 0.125f, x0.y * 0.125f, qh[ks][0], ql[ks][0]);
            split2(x1.x * 0.125f, x1.y * 0.125f, qh[ks][1], ql[ks][1]);
            split2(x2.x * 0.125f, x2.y * 0.125f, qh[ks][2], ql[ks][2]);
            split2(x3.x * 0.125f, x3.y * 0.125f, qh[ks][3], ql[ks][3]);
        }
    }

    float o[8][4];
#pragma unroll
    for (int i = 0; i < 8; i++)
#pragma unroll
        for (int r = 0; r < 4; r++) o[i][r] = 0.f;
    float m0r = -1e30f, m1r = -1e30f, l0 = 0.f, l1 = 0.f;

    for (int j = 0; j < SEQ / 128; j++) {
        // ---- load K tile [128][64] -> Ks (split) ----
        const float* Kt = Kb + (size_t)(j * 128) * EMBED;
#pragma unroll
        for (int i = 0; i < 16; i++) {
            int idx = i * 256 + tid;
            int row = idx >> 5, c2 = idx & 31;
            float2 x = *(const float2*)(Kt + (size_t)row * EMBED + 2 * c2);
            uint32_t hi, lo; split2(x.x, x.y, hi, lo);
            *(uint32_t*)&Ks0[row * FA_LDK + 2 * c2] = hi;
            *(uint32_t*)&Ks1[row * FA_LDK + 2 * c2] = lo;
        }
        // ---- load V tile transposed [64 d][128 kv] -> Vs (hi only) ----
        const float* Vt = Vb + (size_t)(j * 128) * EMBED;
#pragma unroll
        for (int i = 0; i < 16; i++) {
            int idx = i * 256 + tid;
            int d = idx & 63, rp = idx >> 6;        // kv pair 2rp, 2rp+1
            const float* vb0 = Vt + (size_t)(2 * rp) * EMBED + d;
            float x0 = vb0[0];
            float x1 = vb0[EMBED];
            *(uint32_t*)&Vs0[d * FA_LDV + 2 * rp] = pack_h2(x0, x1);
        }
        __syncthreads();

        // ---- S = Q K^T (split 3-plane) ----
        float s[16][4];
#pragma unroll
        for (int f = 0; f < 16; f++)
#pragma unroll
            for (int r = 0; r < 4; r++) s[f][r] = 0.f;
#pragma unroll
        for (int ks = 0; ks < 4; ks++) {
            const int k0 = 16 * ks;
#pragma unroll
            for (int fp = 0; fp < 8; fp++) {
                const int nr = fp * 16 + b_row;
                uint32_t th[4], tl[4];
                ldmx4(th, &Ks0[nr * FA_LDK + k0 + b_kof]);
                ldmx4(tl, &Ks1[nr * FA_LDK + k0 + b_kof]);
                uint32_t bh0[2] = {th[0], th[1]}, bh1[2] = {th[2], th[3]};
                uint32_t bl0[2] = {tl[0], tl[1]}, bl1[2] = {tl[2], tl[3]};
                mma_f16(s[2*fp],   ql[ks], bh0, s[2*fp]);
                mma_f16(s[2*fp],   qh[ks], bl0, s[2*fp]);
                mma_f16(s[2*fp],   qh[ks], bh0, s[2*fp]);
                mma_f16(s[2*fp+1], ql[ks], bh1, s[2*fp+1]);
                mma_f16(s[2*fp+1], qh[ks], bl1, s[2*fp+1]);
                mma_f16(s[2*fp+1], qh[ks], bh1, s[2*fp+1]);
            }
        }

        // ---- online softmax ----
        float mx0 = -1e30f, mx1 = -1e30f;
#pragma unroll
        for (int f = 0; f < 16; f++) {
            mx0 = fmaxf(mx0, fmaxf(s[f][0], s[f][1]));
            mx1 = fmaxf(mx1, fmaxf(s[f][2], s[f][3]));
        }
        mx0 = fmaxf(mx0, __shfl_xor_sync(0xffffffffu, mx0, 1));
        mx0 = fmaxf(mx0, __shfl_xor_sync(0xffffffffu, mx0, 2));
        mx1 = fmaxf(mx1, __shfl_xor_sync(0xffffffffu, mx1, 1));
        mx1 = fmaxf(mx1, __shfl_xor_sync(0xffffffffu, mx1, 2));
        const float mn0 = fmaxf(m0r, mx0), mn1 = fmaxf(m1r, mx1);
        const float cr0 = __expf(m0r - mn0), cr1 = __expf(m1r - mn1);
        m0r = mn0; m1r = mn1;

        float rs0 = 0.f, rs1 = 0.f;
#pragma unroll
        for (int f = 0; f < 16; f++) {
            s[f][0] = __expf(s[f][0] - mn0);
            s[f][1] = __expf(s[f][1] - mn0);
            s[f][2] = __expf(s[f][2] - mn1);
            s[f][3] = __expf(s[f][3] - mn1);
            rs0 += s[f][0] + s[f][1];
            rs1 += s[f][2] + s[f][3];
        }
        rs0 += __shfl_xor_sync(0xffffffffu, rs0, 1);
        rs0 += __shfl_xor_sync(0xffffffffu, rs0, 2);
        rs1 += __shfl_xor_sync(0xffffffffu, rs1, 1);
        rs1 += __shfl_xor_sync(0xffffffffu, rs1, 2);
        l0 = l0 * cr0 + rs0;
        l1 = l1 * cr1 + rs1;
#pragma unroll
        for (int fn = 0; fn < 8; fn++) {
            o[fn][0] *= cr0; o[fn][1] *= cr0;
            o[fn][2] *= cr1; o[fn][3] *= cr1;
        }

        // ---- O += P V : P in-register (fp16), V hi plane only ----
#pragma unroll
        for (int ks = 0; ks < 8; ks++) {
            uint32_t pa[4];
            pa[0] = pack_h2(s[2*ks][0],   s[2*ks][1]);
            pa[1] = pack_h2(s[2*ks][2],   s[2*ks][3]);
            pa[2] = pack_h2(s[2*ks+1][0], s[2*ks+1][1]);
            pa[3] = pack_h2(s[2*ks+1][2], s[2*ks+1][3]);
            const int k0 = 16 * ks;
#pragma unroll
            for (int fp = 0; fp < 4; fp++) {
                const int nr = fp * 16 + b_row;
                uint32_t t[4];
                ldmx4(t, &Vs0[nr * FA_LDV + k0 + b_kof]);
                uint32_t b0[2] = {t[0], t[1]}, b1[2] = {t[2], t[3]};
                mma_f16(o[2*fp],   pa, b0, o[2*fp]);
                mma_f16(o[2*fp+1], pa, b1, o[2*fp+1]);
            }
        }
        __syncthreads();
    }

    // ---- write out ----
    const float inv0 = 1.f / l0, inv1 = 1.f / l1;
    const int r0 = qt * 128 + w * 16 + gq;
    float* Ob0 = outb + ((size_t)(b * SEQ + r0)) * EMBED + h * HDIM;
    float* Ob1 = Ob0 + 8 * (size_t)EMBED;
#pragma unroll
    for (int fn = 0; fn < 8; fn++) {
        const int c = fn * 8 + 2 * tq;
        float2 t0; t0.x = o[fn][0] * inv0; t0.y = o[fn][1] * inv0;
        float2 t1; t1.x = o[fn][2] * inv1; t1.y = o[fn][3] * inv1;
        *(float2*)(Ob0 + c) = t0;
        *(float2*)(Ob1 + c) = t1;
    }
}

// ---------------- host launch ----------------
extern "C" void kernel_launch(void* const* d_in, const int* in_sizes, int n_in,
                              void* d_out, int out_size)
{
    (void)in_sizes; (void)n_in; (void)out_size;
    const float* query = (const float*)d_in[0];
    const float* key   = (const float*)d_in[1];
    const float* value = (const float*)d_in[2];
    const float* Wq    = (const float*)d_in[3];
    const float* Wk    = (const float*)d_in[4];
    const float* Wv    = (const float*)d_in[5];
    const float* Wo    = (const float*)d_in[6];
    float* out = (float*)d_out;

    float *Mcat, *Wo2, *qkv, *at;
    cudaGetSymbolAddress((void**)&Mcat, g_Mcat);
    cudaGetSymbolAddress((void**)&Wo2,  g_Wo2);
    cudaGetSymbolAddress((void**)&qkv,  g_qkv);
    cudaGetSymbolAddress((void**)&at,   g_at);

    // 1: Mcat[0] = Wk^T Wk ; Mcat[1] = Wq^T Wq
    {
        dim3 grid(EMBED / 64, EMBED / 64, 2);
        gemm_f16s<64,64,32,32,32,true,false,false,true><<<grid, 128>>>(
            Wk, Wq, nullptr,  Wk, Wq, nullptr,
            nullptr, nullptr, nullptr,
            Mcat, Mcat + EE, nullptr,
            EMBED, EMBED, EMBED, EMBED, EMBED, EMBED, 1.f, 0.f);
    }
    // 2: Wo2[0] = Wq - Wq@Mcat[0] ; Wo2[1] = Wk - Wk@Mcat[1]
    {
        dim3 grid(EMBED / 64, EMBED / 64, 2);
        gemm_f16s<64,64,32,32,32,false,false,true,true><<<grid, 128>>>(
            Wq, Wk, nullptr,  Mcat, Mcat + EE, nullptr,
            Wq, Wk, nullptr,
            Wo2, Wo2 + EE, nullptr,
            EMBED, EMBED, EMBED, EMBED, EMBED, EMBED, -1.f, 1.f);
    }
    // 3: q = query@Wqo^T ; k = key@Wko^T ; v = value@Wv^T   (A hi-only)
    {
        dim3 grid(EMBED / 128, ROWSM / 128, 3);
        gemm_f16s<128,128,32,64,32,false,true,false,false><<<grid, 256>>>(
            query, key, value,  Wo2, Wo2 + EE, Wv,
            nullptr, nullptr, nullptr,
            qkv, qkv + RME, qkv + 2*RME,
            ROWSM, EMBED, EMBED, EMBED, EMBED, EMBED, 1.f, 0.f);
    }
    // 4: fused flash attention -> at
    {
        cudaFuncSetAttribute(flash_attn, cudaFuncAttributeMaxDynamicSharedMemorySize, FA_SMEM);
        dim3 grid(BATCH * HEADS, SEQ / 128);
        flash_attn<<<grid, 256, FA_SMEM>>>(qkv, at);
    }
    // 5: out = at @ Wo^T  (full split)
    {
        dim3 grid(EMBED / 128, ROWSM / 128, 1);
        gemm_f16s<128,128,32,64,32,false,true,false,true><<<grid, 256>>>(
            at, nullptr, nullptr,  Wo, nullptr, nullptr,
            nullptr, nullptr, nullptr,
            out, nullptr, nullptr,
            ROWSM, EMBED, EMBED, EMBED, EMBED, EMBED, 1.f, 0.f);
    }
}

// round 6
// speedup vs baseline: 3.1943x; 1.0063x over previous
#include <cuda_runtime.h>
#include <cuda_fp16.h>
#include <cstdint>

#define EMBED 1024
#define HEADS 16
#define HDIM  64
#define BATCH 2
#define SEQ   2048
#define ROWSM (BATCH*SEQ)   // 4096
#define EE    (EMBED*EMBED)
#define RME   (ROWSM*EMBED)

// ---------------- scratch (__device__ globals; no allocation allowed) ----------------
__device__ float g_Mcat[2*EE];   // [Wk^T Wk, Wq^T Wq]
__device__ float g_Wo2 [2*EE];   // [Wqo, Wko]
__device__ float g_qkv [3*RME];  // [q, k, v] projected
__device__ float g_at  [RME];    // attention output

// ---------------- helpers ----------------
__device__ __forceinline__ void split_f16(float f, __half& hi, __half& lo) {
    hi = __float2half_rn(f);
    lo = __float2half_rn(f - __half2float(hi));
}
__device__ __forceinline__ void split2(float a, float b, uint32_t& hi, uint32_t& lo) {
    __half2 h = __floats2half2_rn(a, b);
    float2 hf = __half22float2(h);
    __half2 l = __floats2half2_rn(a - hf.x, b - hf.y);
    hi = *reinterpret_cast<uint32_t*>(&h);
    lo = *reinterpret_cast<uint32_t*>(&l);
}
__device__ __forceinline__ uint32_t pack_h2(float a, float b) {
    __half2 h = __floats2half2_rn(a, b);
    return *reinterpret_cast<uint32_t*>(&h);
}

__device__ __forceinline__ void mma_f16(float (&d)[4], const uint32_t (&a)[4],
                                        const uint32_t (&b)[2], const float (&c)[4]) {
    asm volatile(
        "mma.sync.aligned.m16n8k16.row.col.f32.f16.f16.f32 "
        "{%0,%1,%2,%3},{%4,%5,%6,%7},{%8,%9},{%10,%11,%12,%13};\n"
        : "=f"(d[0]), "=f"(d[1]), "=f"(d[2]), "=f"(d[3])
        : "r"(a[0]), "r"(a[1]), "r"(a[2]), "r"(a[3]),
          "r"(b[0]), "r"(b[1]),
          "f"(c[0]), "f"(c[1]), "f"(c[2]), "f"(c[3]));
}

__device__ __forceinline__ uint32_t sptr(const void* p) {
    return (uint32_t)__cvta_generic_to_shared(p);
}
__device__ __forceinline__ void ldmx4(uint32_t* r, const __half* p) {
    asm volatile("ldmatrix.sync.aligned.m8n8.x4.shared.b16 {%0,%1,%2,%3}, [%4];"
        : "=r"(r[0]), "=r"(r[1]), "=r"(r[2]), "=r"(r[3]) : "r"(sptr(p)));
}
__device__ __forceinline__ void cp16(void* s, const void* g) {
    asm volatile("cp.async.cg.shared.global [%0], [%1], 16;"
        :: "r"(sptr(s)), "l"(g));
}
__device__ __forceinline__ void cp_commit() {
    asm volatile("cp.async.commit_group;");
}
__device__ __forceinline__ void cp_wait0() {
    asm volatile("cp.async.wait_group 0;");
}

// ---------------- generic 3-way batched split-fp16 GEMM, cp.async pipelined ----------------
// z = blockIdx.z selects (A,B,Cin,C) pointer set.
// C = alpha * opA(A) * opB(B) [+ beta * Cin]
// SPLITA: A uses hi+lo planes (3 MMAs) else hi only (2 MMAs). B always split.
template<int BM, int BN, int BK, int WM, int WN, bool TA, bool TB, bool HASC, bool SPLITA>
__global__ void __launch_bounds__((BM/WM)*(BN/WN)*32)
gemm_f16s(const float* __restrict__ A0, const float* __restrict__ A1, const float* __restrict__ A2,
          const float* __restrict__ B0, const float* __restrict__ B1, const float* __restrict__ B2,
          const float* __restrict__ Ci0, const float* __restrict__ Ci1, const float* __restrict__ Ci2,
          float* __restrict__ C0, float* __restrict__ C1, float* __restrict__ C2,
          int M, int N, int K, int lda, int ldb, int ldc,
          float alpha, float beta)
{
    constexpr int WARPS_N = BN / WN;
    constexpr int WARPS_M = BM / WM;
    constexpr int NT = WARPS_M * WARPS_N * 32;
    constexpr int MFRAG = WM / 16, NFRAG = WN / 8, KSTEPS = BK / 16;
    constexpr int LDK = BK + 8;
    constexpr int EA = BM * BK / NT, EB = BN * BK / NT;
    constexpr int CA = BM * BK / 4 / NT, CB = BN * BK / 4 / NT;
    constexpr int APLANES = SPLITA ? 2 : 1;

    extern __shared__ char smraw[];
    float*  Ast = (float*)smraw;
    float*  Bst = Ast + BM * BK;
    __half* As  = (__half*)(Bst + BN * BK);
    __half* Bs  = As + APLANES * BM * LDK;

    const int z = blockIdx.z;
    const float* A = (z == 0) ? A0 : ((z == 1) ? A1 : A2);
    const float* B = (z == 0) ? B0 : ((z == 1) ? B1 : B2);
    const float* Cin = (z == 0) ? Ci0 : ((z == 1) ? Ci1 : Ci2);
    float*       C = (z == 0) ? C0 : ((z == 1) ? C1 : C2);

    const int mbase = blockIdx.y * BM;
    const int nbase = blockIdx.x * BN;
    const int tid  = threadIdx.x;
    const int warp = tid >> 5, lane = tid & 31;
    const int wm = warp / WARPS_N, wn = warp % WARPS_N;
    const int gq = lane >> 2, tq = lane & 3;

    float acc[MFRAG][NFRAG][4];
#pragma unroll
    for (int i = 0; i < MFRAG; i++)
#pragma unroll
        for (int j = 0; j < NFRAG; j++)
#pragma unroll
            for (int r = 0; r < 4; r++) acc[i][j][r] = 0.f;

    auto cpAB = [&](int kb) {
#pragma unroll
        for (int i = 0; i < CA; i++) {
            int e = i * NT + tid;
            if (TA) { int k = e / (BM/4), mc = e % (BM/4);
                cp16(Ast + k * BM + 4 * mc, A + (size_t)(kb + k) * lda + mbase + 4 * mc); }
            else    { int m = e / (BK/4), kc = e % (BK/4);
                cp16(Ast + m * BK + 4 * kc, A + (size_t)(mbase + m) * lda + kb + 4 * kc); }
        }
#pragma unroll
        for (int i = 0; i < CB; i++) {
            int e = i * NT + tid;
            if (TB) { int n = e / (BK/4), kc = e % (BK/4);
                cp16(Bst + n * BK + 4 * kc, B + (size_t)(nbase + n) * ldb + kb + 4 * kc); }
            else    { int k = e / (BN/4), nc = e % (BN/4);
                cp16(Bst + k * BN + 4 * nc, B + (size_t)(kb + k) * ldb + nbase + 4 * nc); }
        }
        cp_commit();
    };

    auto convert = [&]() {
#pragma unroll
        for (int i = 0; i < EA; i++) {
            int e = i * NT + tid; int m, k;
            if (TA) { k = e / BM; m = e % BM; } else { m = e / BK; k = e % BK; }
            float f = Ast[e];
            if (SPLITA) {
                __half h, l; split_f16(f, h, l);
                As[m * LDK + k] = h;
                As[BM * LDK + m * LDK + k] = l;
            } else {
                As[m * LDK + k] = __float2half_rn(f);
            }
        }
#pragma unroll
        for (int i = 0; i < EB; i++) {
            int e = i * NT + tid; int n, k;
            if (TB) { n = e / BK; k = e % BK; } else { k = e / BN; n = e % BN; }
            float f = Bst[e];
            __half h, l; split_f16(f, h, l);
            Bs[n * LDK + k] = h;
            Bs[BN * LDK + n * LDK + k] = l;
        }
    };

    // ---- pipeline prologue ----
    cpAB(0);
    cp_wait0(); __syncthreads();
    convert(); __syncthreads();
    if (BK < K) cpAB(BK);

    // ldmatrix lane addressing
    const int a_row = (lane & 15);
    const int a_kof = (lane >> 4) << 3;
    const int b_row = (lane & 7) + (((lane >> 4) & 1) << 3);
    const int b_kof = ((lane >> 3) & 1) << 3;

    for (int kb = 0; kb < K; kb += BK) {
#pragma unroll
        for (int ks = 0; ks < KSTEPS; ks++) {
            const int k0 = ks * 16;
            uint32_t ah[MFRAG][4], al[MFRAG][4];
            uint32_t bh[NFRAG][2], bl[NFRAG][2];
#pragma unroll
            for (int fm = 0; fm < MFRAG; fm++) {
                const int mr = wm * WM + fm * 16 + a_row;
                ldmx4(ah[fm], &As[mr * LDK + k0 + a_kof]);
                if (SPLITA)
                    ldmx4(al[fm], &As[BM * LDK + mr * LDK + k0 + a_kof]);
            }
#pragma unroll
            for (int fp = 0; fp < NFRAG / 2; fp++) {
                const int nr = wn * WN + fp * 16 + b_row;
                uint32_t t[4];
                ldmx4(t, &Bs[nr * LDK + k0 + b_kof]);
                bh[2*fp][0] = t[0]; bh[2*fp][1] = t[1];
                bh[2*fp+1][0] = t[2]; bh[2*fp+1][1] = t[3];
                ldmx4(t, &Bs[BN * LDK + nr * LDK + k0 + b_kof]);
                bl[2*fp][0] = t[0]; bl[2*fp][1] = t[1];
                bl[2*fp+1][0] = t[2]; bl[2*fp+1][1] = t[3];
            }
#pragma unroll
            for (int fm = 0; fm < MFRAG; fm++)
#pragma unroll
                for (int fn = 0; fn < NFRAG; fn++) {
                    if (SPLITA) mma_f16(acc[fm][fn], al[fm], bh[fn], acc[fm][fn]);
                    mma_f16(acc[fm][fn], ah[fm], bl[fn], acc[fm][fn]);
                    mma_f16(acc[fm][fn], ah[fm], bh[fn], acc[fm][fn]);
                }
        }
        // pipeline: stage (kb+BK) was in flight during compute; convert it now
        if (kb + BK < K) {
            cp_wait0(); __syncthreads();
            convert(); __syncthreads();
            if (kb + 2 * BK < K) cpAB(kb + 2 * BK);
        }
    }

    // ---- epilogue ----
#pragma unroll
    for (int fm = 0; fm < MFRAG; fm++) {
        const int m0 = mbase + wm * WM + fm * 16 + gq;
#pragma unroll
        for (int fn = 0; fn < NFRAG; fn++) {
            const int n0 = nbase + wn * WN + fn * 8 + tq * 2;
            float* c0 = C + (size_t)m0 * ldc + n0;
            float* c1 = C + (size_t)(m0 + 8) * ldc + n0;
            if (HASC) {
                const float* ci0 = Cin + (size_t)m0 * ldc + n0;
                const float* ci1 = Cin + (size_t)(m0 + 8) * ldc + n0;
                c0[0] = alpha * acc[fm][fn][0] + beta * ci0[0];
                c0[1] = alpha * acc[fm][fn][1] + beta * ci0[1];
                c1[0] = alpha * acc[fm][fn][2] + beta * ci1[0];
                c1[1] = alpha * acc[fm][fn][3] + beta * ci1[1];
            } else {
                c0[0] = alpha * acc[fm][fn][0];
                c0[1] = alpha * acc[fm][fn][1];
                c1[0] = alpha * acc[fm][fn][2];
                c1[1] = alpha * acc[fm][fn][3];
            }
        }
    }
}

static inline int gemm_smem_bytes(int BM, int BN, int BK, bool splita) {
    int LDK = BK + 8;
    return (BM * BK + BN * BK) * 4 + ((splita ? 2 : 1) * BM + 2 * BN) * LDK * 2;
}

// ---------------- fused flash attention, cp.async pipelined ----------------
// grid(32 heads, 16 q-tiles), 256 threads, BQ=128, BKV=128.
#define FA_LDK 72
#define FA_LDV 136
#define FA_NT  (SEQ/128)
#define FA_SMEM (2*128*64*4 + (2*128*FA_LDK + 64*FA_LDV)*2)

__global__ void __launch_bounds__(256)
flash_attn(const float* __restrict__ qkv, float* __restrict__ outb)
{
    extern __shared__ char smraw[];
    float*  Kst = (float*)smraw;          // [128][64] raw fp32 staging
    float*  Vst = Kst + 128 * 64;         // [128][64]
    __half* Ks0 = (__half*)(Vst + 128 * 64);
    __half* Ks1 = Ks0 + 128 * FA_LDK;
    __half* Vs0 = Ks1 + 128 * FA_LDK;     // transposed [64 d][136 kv]

    const int hh = blockIdx.x;            // 0..31
    const int b = hh >> 4, h = hh & 15;
    const int qt = blockIdx.y;            // 0..15

    const float* Qb = qkv + ((size_t)b * SEQ) * EMBED + h * HDIM;
    const float* Kb = Qb + (size_t)RME;
    const float* Vb = Qb + 2 * (size_t)RME;

    const int tid = threadIdx.x;
    const int w = tid >> 5, lane = tid & 31;
    const int gq = lane >> 2, tq = lane & 3;

    const int b_row = (lane & 7) + (((lane >> 4) & 1) << 3);
    const int b_kof = ((lane >> 3) & 1) << 3;

    auto cpKV = [&](int j) {
        const float* Kt = Kb + (size_t)(j * 128) * EMBED;
        const float* Vt = Vb + (size_t)(j * 128) * EMBED;
#pragma unroll
        for (int i = 0; i < 8; i++) {
            int e = i * 256 + tid;
            int row = e >> 4, c = e & 15;
            cp16(Kst + row * 64 + 4 * c, Kt + (size_t)row * EMBED + 4 * c);
        }
#pragma unroll
        for (int i = 0; i < 8; i++) {
            int e = i * 256 + tid;
            int row = e >> 4, c = e & 15;
            cp16(Vst + row * 64 + 4 * c, Vt + (size_t)row * EMBED + 4 * c);
        }
        cp_commit();
    };

    auto convKV = [&]() {
        // K: split into hi/lo planes, row-major [kv][d]
#pragma unroll
        for (int i = 0; i < 16; i++) {
            int idx = i * 256 + tid;
            int row = idx >> 5, c2 = idx & 31;
            float2 x = *(const float2*)(Kst + row * 64 + 2 * c2);
            uint32_t hi, lo; split2(x.x, x.y, hi, lo);
            *(uint32_t*)&Ks0[row * FA_LDK + 2 * c2] = hi;
            *(uint32_t*)&Ks1[row * FA_LDK + 2 * c2] = lo;
        }
        // V: transpose into [d][kv], hi plane only
#pragma unroll
        for (int i = 0; i < 16; i++) {
            int idx = i * 256 + tid;
            int d = idx & 63, rp = idx >> 6;
            float x0 = Vst[(2 * rp)     * 64 + d];
            float x1 = Vst[(2 * rp + 1) * 64 + d];
            *(uint32_t*)&Vs0[d * FA_LDV + 2 * rp] = pack_h2(x0, x1);
        }
    };

    // ---- Q fragments in registers (pre-scaled, split hi/lo) ----
    uint32_t qh[4][4], ql[4][4];
    {
        const int r0 = qt * 128 + w * 16 + gq;
        const float* Qr0 = Qb + (size_t)r0 * EMBED;
        const float* Qr1 = Qr0 + 8 * (size_t)EMBED;
#pragma unroll
        for (int ks = 0; ks < 4; ks++) {
            const int c = 16 * ks + 2 * tq;
            float2 x0 = *(const float2*)(Qr0 + c);
            float2 x1 = *(const float2*)(Qr1 + c);
            float2 x2 = *(const float2*)(Qr0 + c + 8);
            float2 x3 = *(const float2*)(Qr1 + c + 8);
            split2(x0.x * 0.125f, x0.y * 0.125f, qh[ks][0], ql[ks][0]);
            split2(x1.x * 0.125f, x1.y * 0.125f, qh[ks][1], ql[ks][1]);
            split2(x2.x * 0.125f, x2.y * 0.125f, qh[ks][2], ql[ks][2]);
            split2(x3.x * 0.125f, x3.y * 0.125f, qh[ks][3], ql[ks][3]);
        }
    }

    float o[8][4];
#pragma unroll
    for (int i = 0; i < 8; i++)
#pragma unroll
        for (int r = 0; r < 4; r++) o[i][r] = 0.f;
    float m0r = -1e30f, m1r = -1e30f, l0 = 0.f, l1 = 0.f;

    // ---- pipeline prologue ----
    cpKV(0);
    cp_wait0(); __syncthreads();
    convKV(); __syncthreads();
    cpKV(1);

    for (int j = 0; j < FA_NT; j++) {
        // ---- S = Q K^T (split 3-plane) ----
        float s[16][4];
#pragma unroll
        for (int f = 0; f < 16; f++)
#pragma unroll
            for (int r = 0; r < 4; r++) s[f][r] = 0.f;
#pragma unroll
        for (int ks = 0; ks < 4; ks++) {
            const int k0 = 16 * ks;
#pragma unroll
            for (int fp = 0; fp < 8; fp++) {
                const int nr = fp * 16 + b_row;
                uint32_t th[4], tl[4];
                ldmx4(th, &Ks0[nr * FA_LDK + k0 + b_kof]);
                ldmx4(tl, &Ks1[nr * FA_LDK + k0 + b_kof]);
                uint32_t bh0[2] = {th[0], th[1]}, bh1[2] = {th[2], th[3]};
                uint32_t bl0[2] = {tl[0], tl[1]}, bl1[2] = {tl[2], tl[3]};
                mma_f16(s[2*fp],   ql[ks], bh0, s[2*fp]);
                mma_f16(s[2*fp],   qh[ks], bl0, s[2*fp]);
                mma_f16(s[2*fp],   qh[ks], bh0, s[2*fp]);
                mma_f16(s[2*fp+1], ql[ks], bh1, s[2*fp+1]);
                mma_f16(s[2*fp+1], qh[ks], bl1, s[2*fp+1]);
                mma_f16(s[2*fp+1], qh[ks], bh1, s[2*fp+1]);
            }
        }

        // ---- online softmax ----
        float mx0 = -1e30f, mx1 = -1e30f;
#pragma unroll
        for (int f = 0; f < 16; f++) {
            mx0 = fmaxf(mx0, fmaxf(s[f][0], s[f][1]));
            mx1 = fmaxf(mx1, fmaxf(s[f][2], s[f][3]));
        }
        mx0 = fmaxf(mx0, __shfl_xor_sync(0xffffffffu, mx0, 1));
        mx0 = fmaxf(mx0, __shfl_xor_sync(0xffffffffu, mx0, 2));
        mx1 = fmaxf(mx1, __shfl_xor_sync(0xffffffffu, mx1, 1));
        mx1 = fmaxf(mx1, __shfl_xor_sync(0xffffffffu, mx1, 2));
        const float mn0 = fmaxf(m0r, mx0), mn1 = fmaxf(m1r, mx1);
        const float cr0 = __expf(m0r - mn0), cr1 = __expf(m1r - mn1);
        m0r = mn0; m1r = mn1;

        float rs0 = 0.f, rs1 = 0.f;
#pragma unroll
        for (int f = 0; f < 16; f++) {
            s[f][0] = __expf(s[f][0] - mn0);
            s[f][1] = __expf(s[f][1] - mn0);
            s[f][2] = __expf(s[f][2] - mn1);
            s[f][3] = __expf(s[f][3] - mn1);
            rs0 += s[f][0] + s[f][1];
            rs1 += s[f][2] + s[f][3];
        }
        rs0 += __shfl_xor_sync(0xffffffffu, rs0, 1);
        rs0 += __shfl_xor_sync(0xffffffffu, rs0, 2);
        rs1 += __shfl_xor_sync(0xffffffffu, rs1, 1);
        rs1 += __shfl_xor_sync(0xffffffffu, rs1, 2);
        l0 = l0 * cr0 + rs0;
        l1 = l1 * cr1 + rs1;
#pragma unroll
        for (int fn = 0; fn < 8; fn++) {
            o[fn][0] *= cr0; o[fn][1] *= cr0;
            o[fn][2] *= cr1; o[fn][3] *= cr1;
        }

        // ---- O += P V : P in-register (fp16), V hi plane ----
#pragma unroll
        for (int ks = 0; ks < 8; ks++) {
            uint32_t pa[4];
            pa[0] = pack_h2(s[2*ks][0],   s[2*ks][1]);
            pa[1] = pack_h2(s[2*ks][2],   s[2*ks][3]);
            pa[2] = pack_h2(s[2*ks+1][0], s[2*ks+1][1]);
            pa[3] = pack_h2(s[2*ks+1][2], s[2*ks+1][3]);
            const int k0 = 16 * ks;
#pragma unroll
            for (int fp = 0; fp < 4; fp++) {
                const int nr = fp * 16 + b_row;
                uint32_t t[4];
                ldmx4(t, &Vs0[nr * FA_LDV + k0 + b_kof]);
                uint32_t b0[2] = {t[0], t[1]}, b1[2] = {t[2], t[3]};
                mma_f16(o[2*fp],   pa, b0, o[2*fp]);
                mma_f16(o[2*fp+1], pa, b1, o[2*fp+1]);
            }
        }

        // pipeline: tile j+1 was in flight during compute; convert it now
        if (j + 1 < FA_NT) {
            cp_wait0(); __syncthreads();
            convKV(); __syncthreads();
            if (j + 2 < FA_NT) cpKV(j + 2);
        }
    }

    // ---- write out ----
    const float inv0 = 1.f / l0, inv1 = 1.f / l1;
    const int r0 = qt * 128 + w * 16 + gq;
    float* Ob0 = outb + ((size_t)(b * SEQ + r0)) * EMBED + h * HDIM;
    float* Ob1 = Ob0 + 8 * (size_t)EMBED;
#pragma unroll
    for (int fn = 0; fn < 8; fn++) {
        const int c = fn * 8 + 2 * tq;
        float2 t0; t0.x = o[fn][0] * inv0; t0.y = o[fn][1] * inv0;
        float2 t1; t1.x = o[fn][2] * inv1; t1.y = o[fn][3] * inv1;
        *(float2*)(Ob0 + c) = t0;
        *(float2*)(Ob1 + c) = t1;
    }
}

// ---------------- host launch ----------------
extern "C" void kernel_launch(void* const* d_in, const int* in_sizes, int n_in,
                              void* d_out, int out_size)
{
    (void)in_sizes; (void)n_in; (void)out_size;
    const float* query = (const float*)d_in[0];
    const float* key   = (const float*)d_in[1];
    const float* value = (const float*)d_in[2];
    const float* Wq    = (const float*)d_in[3];
    const float* Wk    = (const float*)d_in[4];
    const float* Wv    = (const float*)d_in[5];
    const float* Wo    = (const float*)d_in[6];
    float* out = (float*)d_out;

    float *Mcat, *Wo2, *qkv, *at;
    cudaGetSymbolAddress((void**)&Mcat, g_Mcat);
    cudaGetSymbolAddress((void**)&Wo2,  g_Wo2);
    cudaGetSymbolAddress((void**)&qkv,  g_qkv);
    cudaGetSymbolAddress((void**)&at,   g_at);

    // 1: Mcat[0] = Wk^T Wk ; Mcat[1] = Wq^T Wq
    {
        auto kfn = gemm_f16s<64,64,32,32,32,true,false,false,true>;
        int sm = gemm_smem_bytes(64,64,32,true);
        cudaFuncSetAttribute(kfn, cudaFuncAttributeMaxDynamicSharedMemorySize, sm);
        dim3 grid(EMBED / 64, EMBED / 64, 2);
        kfn<<<grid, 128, sm>>>(
            Wk, Wq, nullptr,  Wk, Wq, nullptr,
            nullptr, nullptr, nullptr,
            Mcat, Mcat + EE, nullptr,
            EMBED, EMBED, EMBED, EMBED, EMBED, EMBED, 1.f, 0.f);
    }
    // 2: Wo2[0] = Wq - Wq@Mcat[0] ; Wo2[1] = Wk - Wk@Mcat[1]
    {
        auto kfn = gemm_f16s<64,64,32,32,32,false,false,true,true>;
        int sm = gemm_smem_bytes(64,64,32,true);
        cudaFuncSetAttribute(kfn, cudaFuncAttributeMaxDynamicSharedMemorySize, sm);
        dim3 grid(EMBED / 64, EMBED / 64, 2);
        kfn<<<grid, 128, sm>>>(
            Wq, Wk, nullptr,  Mcat, Mcat + EE, nullptr,
            Wq, Wk, nullptr,
            Wo2, Wo2 + EE, nullptr,
            EMBED, EMBED, EMBED, EMBED, EMBED, EMBED, -1.f, 1.f);
    }
    // 3: q = query@Wqo^T ; k = key@Wko^T ; v = value@Wv^T   (A hi-only)
    {
        auto kfn = gemm_f16s<128,128,32,64,32,false,true,false,false>;
        int sm = gemm_smem_bytes(128,128,32,false);
        cudaFuncSetAttribute(kfn, cudaFuncAttributeMaxDynamicSharedMemorySize, sm);
        dim3 grid(EMBED / 128, ROWSM / 128, 3);
        kfn<<<grid, 256, sm>>>(
            query, key, value,  Wo2, Wo2 + EE, Wv,
            nullptr, nullptr, nullptr,
            qkv, qkv + RME, qkv + 2*RME,
            ROWSM, EMBED, EMBED, EMBED, EMBED, EMBED, 1.f, 0.f);
    }
    // 4: fused flash attention -> at
    {
        cudaFuncSetAttribute(flash_attn, cudaFuncAttributeMaxDynamicSharedMemorySize, FA_SMEM);
        dim3 grid(BATCH * HEADS, SEQ / 128);
        flash_attn<<<grid, 256, FA_SMEM>>>(qkv, at);
    }
    // 5: out = at @ Wo^T  (full split)
    {
        auto kfn = gemm_f16s<128,128,32,64,32,false,true,false,true>;
        int sm = gemm_smem_bytes(128,128,32,true);
        cudaFuncSetAttribute(kfn, cudaFuncAttributeMaxDynamicSharedMemorySize, sm);
        dim3 grid(EMBED / 128, ROWSM / 128, 1);
        kfn<<<grid, 256, sm>>>(
            at, nullptr, nullptr,  Wo, nullptr, nullptr,
            nullptr, nullptr, nullptr,
            out, nullptr, nullptr,
            ROWSM, EMBED, EMBED, EMBED, EMBED, EMBED, 1.f, 0.f);
    }
}